// round 2
// baseline (speedup 1.0000x reference)
#include <cuda_runtime.h>
#include <cstdint>

// Problem constants (fixed by the dataset)
#define B_     8192
#define NSITE  256
#define D_     128
#define OUT_   10

// Fused-kernel tiling
#define BM      64          // samples per CTA
#define THREADS 512
#define KC      64          // K-chunk rows double-buffered in smem
#define A_LD    264         // A row stride (floats), 16B-aligned, padded
#define L_LD    132         // left row stride (floats)

// smem floats: left + A + B(2 bufs) + cos/sin
#define SMEM_FLOATS (BM*L_LD + BM*A_LD + 2*KC*D_ + 2*BM)
#define SMEM_BYTES  (SMEM_FLOATS * 4)

// Feature map scratch (site-major for per-step coalesced reads)
__device__ float g_cos[NSITE * B_];   // 8 MB
__device__ float g_sin[NSITE * B_];   // 8 MB

typedef unsigned long long u64;

// ---- Blackwell packed fp32 helpers ----------------------------------------
__device__ __forceinline__ u64 fma2(u64 a, u64 b, u64 c) {
    u64 d;
    asm("fma.rn.f32x2 %0, %1, %2, %3;" : "=l"(d) : "l"(a), "l"(b), "l"(c));
    return d;
}
__device__ __forceinline__ u64 pack2(float x, float y) {
    u64 d;
    asm("mov.b64 %0, {%1, %2};" : "=l"(d) : "f"(x), "f"(y));
    return d;
}
__device__ __forceinline__ void cp16(uint32_t dst, const void* src) {
    asm volatile("cp.async.cg.shared.global [%0], [%1], 16;" :: "r"(dst), "l"(src));
}
__device__ __forceinline__ void cp_commit() {
    asm volatile("cp.async.commit_group;" ::: "memory");
}
__device__ __forceinline__ void cp_wait0() {
    asm volatile("cp.async.wait_group 0;" ::: "memory");
}

// ============================================================================
// Kernel 1: feature map. One warp per sample: min/max over 256 features,
// then phi = (cos(pi/2*xn), sin(pi/2*xn)).
// ============================================================================
__global__ void phi_kernel(const float* __restrict__ x) {
    int warp = (blockIdx.x * blockDim.x + threadIdx.x) >> 5;
    int lane = threadIdx.x & 31;
    if (warp >= B_) return;
    const float* xr = x + (size_t)warp * NSITE;

    float v[8];
    float mn = 3.402823466e38f, mx = -3.402823466e38f;
#pragma unroll
    for (int i = 0; i < 8; i++) {
        v[i] = xr[lane + i * 32];
        mn = fminf(mn, v[i]);
        mx = fmaxf(mx, v[i]);
    }
#pragma unroll
    for (int o = 16; o; o >>= 1) {
        mn = fminf(mn, __shfl_xor_sync(0xffffffffu, mn, o));
        mx = fmaxf(mx, __shfl_xor_sync(0xffffffffu, mx, o));
    }
    float denom = mx - mn + 1e-6f;

#pragma unroll
    for (int i = 0; i < 8; i++) {
        float xn = (v[i] - mn) / denom;
        float s, c;
        sincospif(0.5f * xn, &s, &c);
        int site = lane + i * 32;
        g_cos[(size_t)site * B_ + warp] = c;
        g_sin[(size_t)site * B_ + warp] = s;
    }
}

// ============================================================================
// Kernel 2: fused persistent MPS chain. Each CTA owns BM=64 samples and runs
// all 254 sites locally; left state lives in SMEM the whole time.
// Per step m:  A[r, 2l+d] = phi_d[r] * left[r,l]  (SMEM),
//              left'[r,n] = sum_k A[r,k] * mid[m][k,n]   (f32x2 GEMM)
// mid[m] ([256,128] fp32 = 128 KB) streamed via cp.async double-buffering;
// the full 33 MB mid tensor is L2-resident, so steady-state reads hit L2.
// ============================================================================
__global__ __launch_bounds__(THREADS, 1)
void mps_fused_kernel(const float* __restrict__ first,
                      const float* __restrict__ mid,
                      const float* __restrict__ last,
                      const float* __restrict__ w,
                      const float* __restrict__ bias,
                      float* __restrict__ out) {
    extern __shared__ float smem[];
    float* Lh = smem;                          // [BM][L_LD]
    float* A  = Lh + BM * L_LD;                // [BM][A_LD]
    float* Bs = A  + BM * A_LD;                // [2][KC][128]
    float* cS = Bs + 2 * KC * D_;              // [BM]
    float* sS = cS + BM;                       // [BM]

    const int tid = threadIdx.x;
    const int b0  = blockIdx.x * BM;
    const int tx  = tid & 15;                  // col group: cols tx*8 .. +7
    const int ty  = tid >> 4;                  // row pair:  rows ty*2, ty*2+1

    const uint32_t bs_base = (uint32_t)__cvta_generic_to_shared(Bs);

    // ---- site-0 init: left[r, l] = first[0,l]*c0 + first[1,l]*s0 ----
    if (tid < BM) {
        cS[tid] = g_cos[b0 + tid];
        sS[tid] = g_sin[b0 + tid];
    }
    __syncthreads();
    for (int i = tid; i < BM * D_; i += THREADS) {
        int r = i >> 7, l = i & 127;
        Lh[r * L_LD + l] = first[l] * cS[r] + first[D_ + l] * sS[r];
    }
    __syncthreads();

    // ---- site loop ----
    for (int m = 0; m < NSITE - 2; ++m) {
        const float* Mp = mid + (size_t)m * (2 * D_ * D_);

        // phi for site m+1 (cS/sS reads of prior step fully done: A-build was
        // followed by a barrier before any thread reached the chunk loop)
        if (tid < BM) {
            cS[tid] = g_cos[(size_t)(m + 1) * B_ + b0 + tid];
            sS[tid] = g_sin[(size_t)(m + 1) * B_ + b0 + tid];
        }

        // prefetch K-chunk 0 -> buf 0 (overlaps A-build). buf0's last readers
        // (chunk-2 compute) were released by the chunk-3 barrier last step.
#pragma unroll
        for (int c = 0; c < 4; ++c) {
            int idx = tid + c * THREADS;               // 0..2047 float4s
            cp16(bs_base + idx * 16, Mp + idx * 4);
        }
        cp_commit();

        __syncthreads();   // left (prev step) + cS/sS visible

        // ---- build A: fold cos/sin into left ----
        for (int i = tid; i < BM * D_; i += THREADS) {
            int r = i >> 7, l = i & 127;
            float lv = Lh[r * L_LD + l];
            float2 e = make_float2(cS[r] * lv, sS[r] * lv);
            *(float2*)&A[r * A_LD + 2 * l] = e;
        }
        __syncthreads();   // A visible

        u64 acc[2][4];
#pragma unroll
        for (int r = 0; r < 2; ++r)
#pragma unroll
            for (int c = 0; c < 4; ++c) acc[r][c] = 0ull;

        const float* At = A + (ty * 2) * A_LD;

#pragma unroll 1
        for (int j = 0; j < 4; ++j) {
            cp_wait0();
            __syncthreads();   // chunk j visible; buf (j+1)&1 fully consumed

            if (j < 3) {       // prefetch chunk j+1 into the other buffer
                const float*  src = Mp + (j + 1) * KC * D_;
                uint32_t dst = bs_base + (uint32_t)(((j + 1) & 1) * KC * D_ * 4);
#pragma unroll
                for (int c = 0; c < 4; ++c) {
                    int idx = tid + c * THREADS;
                    cp16(dst + idx * 16, src + idx * 4);
                }
                cp_commit();
            }

            // ---- compute chunk j: k in [j*KC, j*KC+KC) ----
            const float* Bb = Bs + (j & 1) * KC * D_;
            const float* Ar = At + j * KC;
#pragma unroll
            for (int k4 = 0; k4 < KC / 4; ++k4) {
                float4 a0 = *(const float4*)(Ar + k4 * 4);
                float4 a1 = *(const float4*)(Ar + A_LD + k4 * 4);
#pragma unroll
                for (int kk = 0; kk < 4; ++kk) {
                    const float* bp = Bb + (k4 * 4 + kk) * D_ + tx * 8;
                    ulonglong2 bv0 = *(const ulonglong2*)bp;
                    ulonglong2 bv1 = *(const ulonglong2*)(bp + 4);
                    float a0k = (kk == 0) ? a0.x : (kk == 1) ? a0.y
                              : (kk == 2) ? a0.z : a0.w;
                    float a1k = (kk == 0) ? a1.x : (kk == 1) ? a1.y
                              : (kk == 2) ? a1.z : a1.w;
                    u64 d0 = pack2(a0k, a0k);
                    u64 d1 = pack2(a1k, a1k);
                    acc[0][0] = fma2(d0, bv0.x, acc[0][0]);
                    acc[0][1] = fma2(d0, bv0.y, acc[0][1]);
                    acc[0][2] = fma2(d0, bv1.x, acc[0][2]);
                    acc[0][3] = fma2(d0, bv1.y, acc[0][3]);
                    acc[1][0] = fma2(d1, bv0.x, acc[1][0]);
                    acc[1][1] = fma2(d1, bv0.y, acc[1][1]);
                    acc[1][2] = fma2(d1, bv1.x, acc[1][2]);
                    acc[1][3] = fma2(d1, bv1.y, acc[1][3]);
                }
            }
        }

        // ---- writeback: acc -> left (A is dead; next barrier is at step top)
        float* lp0 = Lh + (ty * 2) * L_LD + tx * 8;
        *(ulonglong2*)(lp0)            = make_ulonglong2(acc[0][0], acc[0][1]);
        *(ulonglong2*)(lp0 + 4)        = make_ulonglong2(acc[0][2], acc[0][3]);
        *(ulonglong2*)(lp0 + L_LD)     = make_ulonglong2(acc[1][0], acc[1][1]);
        *(ulonglong2*)(lp0 + L_LD + 4) = make_ulonglong2(acc[1][2], acc[1][3]);
    }

    __syncthreads();

    // ---- final site + linear head ----
    if (tid < BM) {
        int b = b0 + tid;
        float c = g_cos[(size_t)(NSITE - 1) * B_ + b];
        float s = g_sin[(size_t)(NSITE - 1) * B_ + b];
        const float* L = Lh + tid * L_LD;
        float sum = 0.0f;
#pragma unroll 4
        for (int l = 0; l < D_; ++l)
            sum += L[l] * (last[2 * l] * c + last[2 * l + 1] * s);
#pragma unroll
        for (int o = 0; o < OUT_; ++o)
            out[(size_t)b * OUT_ + o] = sum * w[o] + bias[o];
    }
}

// ============================================================================
// Launch: 2 kernels total.
// ============================================================================
extern "C" void kernel_launch(void* const* d_in, const int* in_sizes, int n_in,
                              void* d_out, int out_size) {
    const float* x     = (const float*)d_in[0];  // [B, N]
    const float* first = (const float*)d_in[1];  // [1, 2, D]
    const float* mid   = (const float*)d_in[2];  // [N-2, D, 2, D]
    const float* last  = (const float*)d_in[3];  // [D, 2, 1]
    const float* w     = (const float*)d_in[4];  // [OUT, 1]
    const float* bias  = (const float*)d_in[5];  // [OUT]
    float* out = (float*)d_out;                  // [B, OUT]

    cudaFuncSetAttribute(mps_fused_kernel,
                         cudaFuncAttributeMaxDynamicSharedMemorySize,
                         SMEM_BYTES);

    phi_kernel<<<B_ / 8, 256>>>(x);
    mps_fused_kernel<<<B_ / BM, THREADS, SMEM_BYTES>>>(first, mid, last, w,
                                                       bias, out);
}

// round 3
// speedup vs baseline: 1.6098x; 1.6098x over previous
#include <cuda_runtime.h>
#include <cstdint>

// Problem constants (fixed by the dataset)
#define B_     8192
#define NSITE  256
#define D_     128
#define OUT_   10

// Fused-kernel tiling
#define BM      64          // samples per CTA -> grid = 128 CTAs
#define THREADS 256         // 8 warps
#define KC      64          // K-chunk rows double-buffered in smem
#define LT_LD   68          // left^T row stride (floats): 16B aligned, 4-way-at-worst banks
#define AT_LD   68          // A^T row stride (floats)

// smem floats: Lt[128][LT_LD] + At[256][AT_LD] + B[2][KC][128] + cS/sS
#define SMEM_FLOATS (128*LT_LD + 256*AT_LD + 2*KC*D_ + 2*BM)
#define SMEM_BYTES  (SMEM_FLOATS * 4)

// Feature map scratch (site-major for per-step coalesced reads)
__device__ float g_cos[NSITE * B_];   // 8 MB
__device__ float g_sin[NSITE * B_];   // 8 MB

typedef unsigned long long u64;

// ---- Blackwell packed fp32 helpers ----------------------------------------
__device__ __forceinline__ u64 fma2(u64 a, u64 b, u64 c) {
    u64 d;
    asm("fma.rn.f32x2 %0, %1, %2, %3;" : "=l"(d) : "l"(a), "l"(b), "l"(c));
    return d;
}
__device__ __forceinline__ u64 pack2(float x, float y) {
    u64 d;
    asm("mov.b64 %0, {%1, %2};" : "=l"(d) : "f"(x), "f"(y));
    return d;
}
__device__ __forceinline__ float2 unpack2(u64 v) {
    float2 r;
    asm("mov.b64 {%0, %1}, %2;" : "=f"(r.x), "=f"(r.y) : "l"(v));
    return r;
}
__device__ __forceinline__ void cp16(uint32_t dst, const void* src) {
    asm volatile("cp.async.cg.shared.global [%0], [%1], 16;" :: "r"(dst), "l"(src));
}
__device__ __forceinline__ void cp_commit() {
    asm volatile("cp.async.commit_group;" ::: "memory");
}
__device__ __forceinline__ void cp_wait0() {
    asm volatile("cp.async.wait_group 0;" ::: "memory");
}

// ============================================================================
// Kernel 1: feature map. One warp per sample: min/max over 256 features,
// then phi = (cos(pi/2*xn), sin(pi/2*xn)). Site-major output.
// ============================================================================
__global__ void phi_kernel(const float* __restrict__ x) {
    int warp = (blockIdx.x * blockDim.x + threadIdx.x) >> 5;
    int lane = threadIdx.x & 31;
    if (warp >= B_) return;
    const float* xr = x + (size_t)warp * NSITE;

    float v[8];
    float mn = 3.402823466e38f, mx = -3.402823466e38f;
#pragma unroll
    for (int i = 0; i < 8; i++) {
        v[i] = xr[lane + i * 32];
        mn = fminf(mn, v[i]);
        mx = fmaxf(mx, v[i]);
    }
#pragma unroll
    for (int o = 16; o; o >>= 1) {
        mn = fminf(mn, __shfl_xor_sync(0xffffffffu, mn, o));
        mx = fmaxf(mx, __shfl_xor_sync(0xffffffffu, mx, o));
    }
    float denom = mx - mn + 1e-6f;

#pragma unroll
    for (int i = 0; i < 8; i++) {
        float xn = (v[i] - mn) / denom;
        float s, c;
        sincospif(0.5f * xn, &s, &c);
        int site = lane + i * 32;
        g_cos[(size_t)site * B_ + warp] = c;
        g_sin[(size_t)site * B_ + warp] = s;
    }
}

// ============================================================================
// Kernel 2: fused persistent MPS chain. CTA owns BM=64 samples; left state
// lives in SMEM, TRANSPOSED: Lt[l_bond][r_sample]. Per step:
//   build At[k][r] = phi_{k&1}[r] * Lt[k>>1][r]     (k = 0..255)
//   Lt'[n][r] = sum_k At[k][r] * mid[m][k][n]       (f32x2 GEMM)
// mid[m] streamed via cp.async double-buffer (KC=64 rows per chunk);
// the full 33 MB mid tensor stays L2-resident.
// Thread tile 4 rows x 8 cols; warp = 2 row-groups x 16 col-groups:
//   At loads broadcast (1 wf), B loads conflict-free contiguous.
// ============================================================================
__global__ __launch_bounds__(THREADS, 1)
void mps_fused_kernel(const float* __restrict__ first,
                      const float* __restrict__ mid,
                      const float* __restrict__ last,
                      const float* __restrict__ w,
                      const float* __restrict__ bias,
                      float* __restrict__ out) {
    extern __shared__ float smem[];
    float* Lt = smem;                       // [128][LT_LD]
    float* At = Lt + 128 * LT_LD;           // [256][AT_LD]
    float* Bs = At + 256 * AT_LD;           // [2][KC][128]
    float* cS = Bs + 2 * KC * D_;           // [BM]
    float* sS = cS + BM;                    // [BM]

    const int tid = threadIdx.x;
    const int b0  = blockIdx.x * BM;
    const int tx  = tid & 15;               // col group: cols tx*8 .. +7
    const int ty  = tid >> 4;               // row group: rows ty*4 .. +3
    const int r0  = ty * 4;
    const int c0  = tx * 8;

    const uint32_t bs_base = (uint32_t)__cvta_generic_to_shared(Bs);

    // ---- site-0 init: Lt[l][r] = first[0,l]*c0_r + first[1,l]*s0_r ----
    if (tid < BM) {
        cS[tid] = g_cos[b0 + tid];
        sS[tid] = g_sin[b0 + tid];
    }
    __syncthreads();
    for (int i = tid; i < 128 * BM; i += THREADS) {
        int l = i >> 6, r = i & 63;
        Lt[l * LT_LD + r] = first[l] * cS[r] + first[D_ + l] * sS[r];
    }
    __syncthreads();

    // ---- site loop ----
    for (int m = 0; m < NSITE - 2; ++m) {
        const float* Mp = mid + (size_t)m * (2 * D_ * D_);

        // phi for site m+1 (safe: cS/sS only read in build, after barrier)
        if (tid < BM) {
            cS[tid] = g_cos[(size_t)(m + 1) * B_ + b0 + tid];
            sS[tid] = g_sin[(size_t)(m + 1) * B_ + b0 + tid];
        }

        // prefetch chunk 0 -> buf 0 (overlaps A-build below). buf0's last
        // readers (chunk-2 compute) drained at the chunk-3 barrier last step.
#pragma unroll
        for (int c = 0; c < 8; ++c) {
            int idx = tid + c * THREADS;           // 0..2047 float4s
            cp16(bs_base + idx * 16, Mp + idx * 4);
        }
        cp_commit();

        __syncthreads();   // Lt (prev step) + cS/sS visible

        // ---- build At[k][r] = phi_{k&1}[r] * Lt[k>>1][r] ----
        {
            int k  = tid >> 1;
            int rh = (tid & 1) * 32;
#pragma unroll
            for (int half = 0; half < 2; ++half) {
                const float* ph   = (k & 1) ? sS : cS;
                const float* Lrow = Lt + (k >> 1) * LT_LD + rh;
                float*       Arow = At + k * AT_LD + rh;
#pragma unroll
                for (int q = 0; q < 8; ++q) {
                    float4 Lv = *(const float4*)(Lrow + q * 4);
                    float4 Pv = *(const float4*)(ph + rh + q * 4);
                    *(float4*)(Arow + q * 4) = make_float4(
                        Lv.x * Pv.x, Lv.y * Pv.y, Lv.z * Pv.z, Lv.w * Pv.w);
                }
                k += 128;
            }
        }
        __syncthreads();   // At visible

        u64 acc[4][4];
#pragma unroll
        for (int r = 0; r < 4; ++r)
#pragma unroll
            for (int p = 0; p < 4; ++p) acc[r][p] = 0ull;

#pragma unroll 1
        for (int j = 0; j < 4; ++j) {
            cp_wait0();
            __syncthreads();   // chunk j in; buf (j+1)&1 fully consumed

            if (j < 3) {       // prefetch chunk j+1 into the other buffer
                const float* src = Mp + (j + 1) * KC * D_;
                uint32_t dst = bs_base + (uint32_t)(((j + 1) & 1) * KC * D_ * 4);
#pragma unroll
                for (int c = 0; c < 8; ++c) {
                    int idx = tid + c * THREADS;
                    cp16(dst + idx * 16, src + idx * 4);
                }
                cp_commit();
            }

            // ---- compute chunk j ----
            const float* Bb = Bs + (j & 1) * KC * D_ + c0;
            const float* Ab = At + (j * KC) * AT_LD + r0;
#pragma unroll 8
            for (int k = 0; k < KC; ++k) {
                float4 a = *(const float4*)(Ab + k * AT_LD);          // bcast
                ulonglong2 bq0 = *(const ulonglong2*)(Bb + k * D_);    // cols 0-3
                ulonglong2 bq1 = *(const ulonglong2*)(Bb + k * D_ + 4);// cols 4-7
                u64 d0 = pack2(a.x, a.x);
                u64 d1 = pack2(a.y, a.y);
                u64 d2 = pack2(a.z, a.z);
                u64 d3 = pack2(a.w, a.w);
                acc[0][0] = fma2(d0, bq0.x, acc[0][0]);
                acc[0][1] = fma2(d0, bq0.y, acc[0][1]);
                acc[0][2] = fma2(d0, bq1.x, acc[0][2]);
                acc[0][3] = fma2(d0, bq1.y, acc[0][3]);
                acc[1][0] = fma2(d1, bq0.x, acc[1][0]);
                acc[1][1] = fma2(d1, bq0.y, acc[1][1]);
                acc[1][2] = fma2(d1, bq1.x, acc[1][2]);
                acc[1][3] = fma2(d1, bq1.y, acc[1][3]);
                acc[2][0] = fma2(d2, bq0.x, acc[2][0]);
                acc[2][1] = fma2(d2, bq0.y, acc[2][1]);
                acc[2][2] = fma2(d2, bq1.x, acc[2][2]);
                acc[2][3] = fma2(d2, bq1.y, acc[2][3]);
                acc[3][0] = fma2(d3, bq0.x, acc[3][0]);
                acc[3][1] = fma2(d3, bq0.y, acc[3][1]);
                acc[3][2] = fma2(d3, bq1.x, acc[3][2]);
                acc[3][3] = fma2(d3, bq1.y, acc[3][3]);
            }
        }

        // ---- writeback acc -> Lt' (transposed), XOR-staggered vs banks ----
        // Safe without barrier: other warps only read At/Bs until step top.
#pragma unroll
        for (int cc = 0; cc < 8; ++cc) {
            int c = cc ^ (tx & 7);
            int p = c >> 1;
            float v0, v1, v2, v3;
            if (c & 1) {
                v0 = unpack2(acc[0][p]).y; v1 = unpack2(acc[1][p]).y;
                v2 = unpack2(acc[2][p]).y; v3 = unpack2(acc[3][p]).y;
            } else {
                v0 = unpack2(acc[0][p]).x; v1 = unpack2(acc[1][p]).x;
                v2 = unpack2(acc[2][p]).x; v3 = unpack2(acc[3][p]).x;
            }
            *(float4*)&Lt[(c0 + c) * LT_LD + r0] = make_float4(v0, v1, v2, v3);
        }
    }

    __syncthreads();

    // ---- final site + linear head ----
    if (tid < BM) {
        int b = b0 + tid;
        float c = g_cos[(size_t)(NSITE - 1) * B_ + b];
        float s = g_sin[(size_t)(NSITE - 1) * B_ + b];
        float sum = 0.0f;
#pragma unroll 4
        for (int l = 0; l < D_; ++l)
            sum += Lt[l * LT_LD + tid] * (last[2 * l] * c + last[2 * l + 1] * s);
#pragma unroll
        for (int o = 0; o < OUT_; ++o)
            out[(size_t)b * OUT_ + o] = sum * w[o] + bias[o];
    }
}

// ============================================================================
// Launch: 2 kernels total.
// ============================================================================
extern "C" void kernel_launch(void* const* d_in, const int* in_sizes, int n_in,
                              void* d_out, int out_size) {
    const float* x     = (const float*)d_in[0];  // [B, N]
    const float* first = (const float*)d_in[1];  // [1, 2, D]
    const float* mid   = (const float*)d_in[2];  // [N-2, D, 2, D]
    const float* last  = (const float*)d_in[3];  // [D, 2, 1]
    const float* w     = (const float*)d_in[4];  // [OUT, 1]
    const float* bias  = (const float*)d_in[5];  // [OUT]
    float* out = (float*)d_out;                  // [B, OUT]

    cudaFuncSetAttribute(mps_fused_kernel,
                         cudaFuncAttributeMaxDynamicSharedMemorySize,
                         SMEM_BYTES);

    phi_kernel<<<B_ / 8, 256>>>(x);
    mps_fused_kernel<<<B_ / BM, THREADS, SMEM_BYTES>>>(first, mid, last, w,
                                                       bias, out);
}

// round 4
// speedup vs baseline: 2.3020x; 1.4299x over previous
#include <cuda_runtime.h>
#include <cstdint>

// Problem constants (fixed by the dataset)
#define B_     8192
#define NSITE  256
#define D_     128
#define OUT_   10

// Fused-kernel tiling
#define BM      64          // samples per CTA -> grid = 128 CTAs
#define THREADS 512         // 16 warps, 4 per SMSP
#define KC      32          // k-rows per B chunk (16 l values), 8 chunks/step
#define NCH     8           // chunks per step
#define LDD     132         // duplicated-left row stride (floats): 2*BM + 4 pad

// smem floats: LtD[2][128][LDD] ping-pong + Bs[2][KC][128] + cS/sS
#define SMEM_FLOATS (2*128*LDD + 2*KC*D_ + 2*BM)
#define SMEM_BYTES  (SMEM_FLOATS * 4)

// Feature map scratch (site-major for per-step coalesced reads)
__device__ float g_cos[NSITE * B_];   // 8 MB
__device__ float g_sin[NSITE * B_];   // 8 MB

typedef unsigned long long u64;

// ---- Blackwell packed fp32 helpers ----------------------------------------
__device__ __forceinline__ u64 fma2(u64 a, u64 b, u64 c) {
    u64 d;
    asm("fma.rn.f32x2 %0, %1, %2, %3;" : "=l"(d) : "l"(a), "l"(b), "l"(c));
    return d;
}
__device__ __forceinline__ u64 mul2(u64 a, u64 b) {
    u64 d;
    asm("mul.rn.f32x2 %0, %1, %2;" : "=l"(d) : "l"(a), "l"(b));
    return d;
}
__device__ __forceinline__ u64 pack2(float x, float y) {
    u64 d;
    asm("mov.b64 %0, {%1, %2};" : "=l"(d) : "f"(x), "f"(y));
    return d;
}
__device__ __forceinline__ float2 unpack2(u64 v) {
    float2 r;
    asm("mov.b64 {%0, %1}, %2;" : "=f"(r.x), "=f"(r.y) : "l"(v));
    return r;
}
__device__ __forceinline__ void cp16(uint32_t dst, const void* src) {
    asm volatile("cp.async.cg.shared.global [%0], [%1], 16;" :: "r"(dst), "l"(src));
}
__device__ __forceinline__ void cp_commit() {
    asm volatile("cp.async.commit_group;" ::: "memory");
}
__device__ __forceinline__ void cp_wait0() {
    asm volatile("cp.async.wait_group 0;" ::: "memory");
}

// ============================================================================
// Kernel 1: feature map. One warp per sample: min/max over 256 features,
// then phi = (cos(pi/2*xn), sin(pi/2*xn)). Site-major output.
// ============================================================================
__global__ void phi_kernel(const float* __restrict__ x) {
    int warp = (blockIdx.x * blockDim.x + threadIdx.x) >> 5;
    int lane = threadIdx.x & 31;
    if (warp >= B_) return;
    const float* xr = x + (size_t)warp * NSITE;

    float v[8];
    float mn = 3.402823466e38f, mx = -3.402823466e38f;
#pragma unroll
    for (int i = 0; i < 8; i++) {
        v[i] = xr[lane + i * 32];
        mn = fminf(mn, v[i]);
        mx = fmaxf(mx, v[i]);
    }
#pragma unroll
    for (int o = 16; o; o >>= 1) {
        mn = fminf(mn, __shfl_xor_sync(0xffffffffu, mn, o));
        mx = fmaxf(mx, __shfl_xor_sync(0xffffffffu, mx, o));
    }
    float denom = mx - mn + 1e-6f;

#pragma unroll
    for (int i = 0; i < 8; i++) {
        float xn = (v[i] - mn) / denom;
        float s, c;
        sincospif(0.5f * xn, &s, &c);
        int site = lane + i * 32;
        g_cos[(size_t)site * B_ + warp] = c;
        g_sin[(size_t)site * B_ + warp] = s;
    }
}

// ============================================================================
// Kernel 2: fused persistent MPS chain with PARITY-SPLIT accumulation.
//   left'[r,n] = c_r * sum_l Lt[l,r]*M[2l,n]  +  s_r * sum_l Lt[l,r]*M[2l+1,n]
// -> no A materialization; phi applied once per step at writeback.
// left stored DUPLICATED (LtD[l][2r]=LtD[l][2r+1]) so the broadcast operand
// loads directly as packed f32x2 pairs: zero dup-MOVs in the inner loop.
// 16 warps: 4 row-strips(16) x 4 col-strips(32). Thread: 4 rows x 4 cols x 2
// parities (16 u64 accs). Per l per warp: 2 LDS.128 (A) + 2 LDS.128 (B rows
// 2l, 2l+1) + 16 fma2, all conflict-free.
// mid[m] streamed via cp.async double-buffer (KC=32 rows/chunk, 8 chunks).
// ============================================================================
__global__ __launch_bounds__(THREADS, 1)
void mps_fused_kernel(const float* __restrict__ first,
                      const float* __restrict__ mid,
                      const float* __restrict__ last,
                      const float* __restrict__ w,
                      const float* __restrict__ bias,
                      float* __restrict__ out) {
    extern __shared__ float smem[];
    float* LtD = smem;                     // [2][128][LDD]
    float* Bs  = LtD + 2 * 128 * LDD;      // [2][KC][128]
    float* cS  = Bs + 2 * KC * D_;         // [BM]
    float* sS  = cS + BM;                  // [BM]

    const int tid    = threadIdx.x;
    const int b0     = blockIdx.x * BM;
    const int lane   = tid & 31;
    const int wid    = tid >> 5;
    const int cstrip = wid >> 2;           // 0..3  (32-col strip)
    const int rstrip = wid & 3;            // 0..3  (16-row strip)
    const int g      = lane >> 3;          // 0..3  (4-row group)
    const int tc     = lane & 7;           // 0..7  (4-col group)
    const int r0     = rstrip * 16 + g * 4;        // first sample row
    const int c0     = cstrip * 32 + tc * 4;       // first output col

    const uint32_t bs_base = (uint32_t)__cvta_generic_to_shared(Bs);

    // ---- site-0 init into LtD buf 0 (duplicated layout) ----
    if (tid < BM) {
        cS[tid] = g_cos[b0 + tid];
        sS[tid] = g_sin[b0 + tid];
    }
    __syncthreads();
    for (int i = tid; i < 128 * BM; i += THREADS) {
        int l = i >> 6, r = i & 63;
        float v = first[l] * cS[r] + first[D_ + l] * sS[r];
        LtD[l * LDD + 2 * r]     = v;
        LtD[l * LDD + 2 * r + 1] = v;
    }

    // ---- site loop ----
    for (int m = 0; m < NSITE - 2; ++m) {
        const float* Mp   = mid + (size_t)m * (2 * D_ * D_);
        const float* Lin  = LtD + (m & 1) * 128 * LDD;
        float*       Lout = LtD + ((m & 1) ^ 1) * 128 * LDD;

        __syncthreads();   // prev writeback + prev cS-reads complete

        if (tid < BM) {    // phi for site m+1
            cS[tid] = g_cos[(size_t)(m + 1) * B_ + b0 + tid];
            sS[tid] = g_sin[(size_t)(m + 1) * B_ + b0 + tid];
        }

        // prefetch chunk 0 -> buf 0 (its last readers drained at chunk-7 sync)
#pragma unroll
        for (int c = 0; c < 2; ++c) {
            int idx = tid + c * THREADS;              // 0..1023 float4s
            cp16(bs_base + idx * 16, Mp + idx * 4);
        }
        cp_commit();

        u64 accE[4][2], accO[4][2];
#pragma unroll
        for (int r = 0; r < 4; ++r) {
            accE[r][0] = accE[r][1] = 0ull;
            accO[r][0] = accO[r][1] = 0ull;
        }

        const float* aP = Lin + rstrip * 32 + g * 8;   // + l*LDD (dup index 2*r0)

#pragma unroll 1
        for (int j = 0; j < NCH; ++j) {
            cp_wait0();
            __syncthreads();   // chunk j landed; other buf fully consumed

            if (j < NCH - 1) {  // prefetch chunk j+1 into the other buffer
                const float* src = Mp + (j + 1) * KC * D_;
                uint32_t dst = bs_base + (uint32_t)(((j + 1) & 1) * KC * D_ * 4);
#pragma unroll
                for (int c = 0; c < 2; ++c) {
                    int idx = tid + c * THREADS;
                    cp16(dst + idx * 16, src + idx * 4);
                }
                cp_commit();
            }

            // ---- compute chunk j: l in [j*16, j*16+16) ----
            const float* aC = aP + (j * (KC / 2)) * LDD;
            const float* bP = Bs + (j & 1) * KC * D_ + c0;
#pragma unroll
            for (int ll = 0; ll < KC / 2; ++ll) {
                ulonglong2 a01 = *(const ulonglong2*)(aC);        // rows r0,r0+1 (dup)
                ulonglong2 a23 = *(const ulonglong2*)(aC + 4);    // rows r0+2,r0+3
                ulonglong2 bE  = *(const ulonglong2*)(bP);        // row 2l, cols c0..c0+3
                ulonglong2 bO  = *(const ulonglong2*)(bP + D_);   // row 2l+1
                accE[0][0] = fma2(a01.x, bE.x, accE[0][0]);
                accE[0][1] = fma2(a01.x, bE.y, accE[0][1]);
                accE[1][0] = fma2(a01.y, bE.x, accE[1][0]);
                accE[1][1] = fma2(a01.y, bE.y, accE[1][1]);
                accE[2][0] = fma2(a23.x, bE.x, accE[2][0]);
                accE[2][1] = fma2(a23.x, bE.y, accE[2][1]);
                accE[3][0] = fma2(a23.y, bE.x, accE[3][0]);
                accE[3][1] = fma2(a23.y, bE.y, accE[3][1]);
                accO[0][0] = fma2(a01.x, bO.x, accO[0][0]);
                accO[0][1] = fma2(a01.x, bO.y, accO[0][1]);
                accO[1][0] = fma2(a01.y, bO.x, accO[1][0]);
                accO[1][1] = fma2(a01.y, bO.y, accO[1][1]);
                accO[2][0] = fma2(a23.x, bO.x, accO[2][0]);
                accO[2][1] = fma2(a23.x, bO.y, accO[2][1]);
                accO[3][0] = fma2(a23.y, bO.x, accO[3][0]);
                accO[3][1] = fma2(a23.y, bO.y, accO[3][1]);
                aC += LDD;
                bP += 2 * D_;
            }
        }

        // ---- writeback: left'[r,n] = c_r*accE + s_r*accO, to Lout (dup'd) ----
        {
            float4 cv = *(const float4*)(cS + r0);
            float4 sv = *(const float4*)(sS + r0);
            u64 res[4][2];
#pragma unroll
            for (int r = 0; r < 4; ++r) {
                float cr = (r == 0) ? cv.x : (r == 1) ? cv.y : (r == 2) ? cv.z : cv.w;
                float sr = (r == 0) ? sv.x : (r == 1) ? sv.y : (r == 2) ? sv.z : sv.w;
                u64 cp_ = pack2(cr, cr);
                u64 sp_ = pack2(sr, sr);
                res[r][0] = fma2(cp_, accE[r][0], mul2(sp_, accO[r][0]));
                res[r][1] = fma2(cp_, accE[r][1], mul2(sp_, accO[r][1]));
            }
            // transpose 4x4 block and store duplicated rows per output col
#pragma unroll
            for (int i = 0; i < 4; ++i) {
                int n = c0 + i;
                float w0, w1, w2, w3;
                if (i & 1) {
                    w0 = unpack2(res[0][i >> 1]).y; w1 = unpack2(res[1][i >> 1]).y;
                    w2 = unpack2(res[2][i >> 1]).y; w3 = unpack2(res[3][i >> 1]).y;
                } else {
                    w0 = unpack2(res[0][i >> 1]).x; w1 = unpack2(res[1][i >> 1]).x;
                    w2 = unpack2(res[2][i >> 1]).x; w3 = unpack2(res[3][i >> 1]).x;
                }
                float* dst = Lout + n * LDD + 2 * r0;
                *(float4*)(dst)     = make_float4(w0, w0, w1, w1);
                *(float4*)(dst + 4) = make_float4(w2, w2, w3, w3);
            }
        }
    }

    __syncthreads();

    // ---- final site + linear head (final state is in buf (NSITE-2)&1 == 0) ----
    if (tid < BM) {
        const float* Lf = LtD + ((NSITE - 2) & 1) * 128 * LDD;
        int b = b0 + tid;
        float c = g_cos[(size_t)(NSITE - 1) * B_ + b];
        float s = g_sin[(size_t)(NSITE - 1) * B_ + b];
        float sum = 0.0f;
#pragma unroll 4
        for (int l = 0; l < D_; ++l)
            sum += Lf[l * LDD + 2 * tid] * (last[2 * l] * c + last[2 * l + 1] * s);
#pragma unroll
        for (int o = 0; o < OUT_; ++o)
            out[(size_t)b * OUT_ + o] = sum * w[o] + bias[o];
    }
}

// ============================================================================
// Launch: 2 kernels total.
// ============================================================================
extern "C" void kernel_launch(void* const* d_in, const int* in_sizes, int n_in,
                              void* d_out, int out_size) {
    const float* x     = (const float*)d_in[0];  // [B, N]
    const float* first = (const float*)d_in[1];  // [1, 2, D]
    const float* mid   = (const float*)d_in[2];  // [N-2, D, 2, D]
    const float* last  = (const float*)d_in[3];  // [D, 2, 1]
    const float* w     = (const float*)d_in[4];  // [OUT, 1]
    const float* bias  = (const float*)d_in[5];  // [OUT]
    float* out = (float*)d_out;                  // [B, OUT]

    cudaFuncSetAttribute(mps_fused_kernel,
                         cudaFuncAttributeMaxDynamicSharedMemorySize,
                         SMEM_BYTES);

    phi_kernel<<<B_ / 8, 256>>>(x);
    mps_fused_kernel<<<B_ / BM, THREADS, SMEM_BYTES>>>(first, mid, last, w,
                                                       bias, out);
}

// round 6
// speedup vs baseline: 7.5828x; 3.2940x over previous
#include <cuda_runtime.h>
#include <cuda_bf16.h>
#include <cstdint>

// Problem constants
#define B_     8192
#define NSITE  256
#define D_     128
#define OUT_   10
#define NSTEP  254
#define BM     64            // samples per CTA
#define NCTA   (B_ / BM)     // 128 CTAs
#define THREADS 256          // 8 warps
#define TOTQ   (NSTEP * 4)   // total 32KB B-chunks streamed

// smem byte offsets
#define SM_AH   0            // A-hi bf16 tiles: 64x128 -> 16 KB
#define SM_AL   16384        // A-lo
#define SM_B    32768        // 3 x 32768 B-chunk ring
#define SM_CS   131072       // cos site m+1 [64]
#define SM_SS   131328
#define SM_C2   131584       // cos site 255 [64]
#define SM_S2   131840
#define SM_LAST 132096       // last tensor staged [256]
#define SM_RED  133120       // final reduce [4][64]
#define SMEM_TOTAL 134144

// Scratch globals
__device__ float g_cos[NSITE * B_];                      // 8 MB
__device__ float g_sin[NSITE * B_];                      // 8 MB
// Pre-split B: [step][chunk(4)][mat{He,Ho,Le,Lo}][4096 bf16 tile-contiguous]
__device__ __nv_bfloat16 g_B[(size_t)NSTEP * 65536];     // 33.3 MB

// ---------------------------------------------------------------------------
// Base-ISA asm helpers (no 'a'-suffix features)
// ---------------------------------------------------------------------------
__device__ __forceinline__ uint32_t smem_u32(const void* p) {
    uint32_t a;
    asm("{ .reg .u64 t; cvta.to.shared.u64 t, %1; cvt.u32.u64 %0, t; }"
        : "=r"(a) : "l"(p));
    return a;
}
__device__ __forceinline__ void cp16(uint32_t dst, const void* src) {
    asm volatile("cp.async.cg.shared.global [%0], [%1], 16;" :: "r"(dst), "l"(src));
}
__device__ __forceinline__ void cp_commit() {
    asm volatile("cp.async.commit_group;" ::: "memory");
}
__device__ __forceinline__ void cp_wait1() {
    asm volatile("cp.async.wait_group 1;" ::: "memory");
}
__device__ __forceinline__ void ldsm4(uint32_t* r, uint32_t a) {
    asm volatile("ldmatrix.sync.aligned.m8n8.x4.shared.b16 {%0,%1,%2,%3}, [%4];"
                 : "=r"(r[0]), "=r"(r[1]), "=r"(r[2]), "=r"(r[3]) : "r"(a));
}
__device__ __forceinline__ void ldsm4t(uint32_t* r, uint32_t a) {
    asm volatile("ldmatrix.sync.aligned.m8n8.x4.trans.shared.b16 {%0,%1,%2,%3}, [%4];"
                 : "=r"(r[0]), "=r"(r[1]), "=r"(r[2]), "=r"(r[3]) : "r"(a));
}
__device__ __forceinline__ void stsm4(uint32_t a, uint32_t r0, uint32_t r1,
                                      uint32_t r2, uint32_t r3) {
    asm volatile("stmatrix.sync.aligned.m8n8.x4.shared.b16 [%0], {%1,%2,%3,%4};"
                 :: "r"(a), "r"(r0), "r"(r1), "r"(r2), "r"(r3) : "memory");
}
__device__ __forceinline__ void mma16816(float* c, const uint32_t* a,
                                         const uint32_t* b) {
    asm volatile(
        "mma.sync.aligned.m16n8k16.row.col.f32.bf16.bf16.f32 "
        "{%0,%1,%2,%3}, {%4,%5,%6,%7}, {%8,%9}, {%0,%1,%2,%3};"
        : "+f"(c[0]), "+f"(c[1]), "+f"(c[2]), "+f"(c[3])
        : "r"(a[0]), "r"(a[1]), "r"(a[2]), "r"(a[3]), "r"(b[0]), "r"(b[1]));
}
// hi/lo bf16 split of (r0, r1) -> packed bf16x2 (low half = r0)
__device__ __forceinline__ void split2(float r0, float r1,
                                       uint32_t& h, uint32_t& l) {
    uint32_t hp;
    asm("cvt.rn.satfinite.bf16x2.f32 %0, %1, %2;" : "=r"(hp) : "f"(r1), "f"(r0));
    float f0 = __uint_as_float(hp << 16);
    float f1 = __uint_as_float(hp & 0xFFFF0000u);
    float l0 = r0 - f0, l1 = r1 - f1;
    uint32_t lp;
    asm("cvt.rn.satfinite.bf16x2.f32 %0, %1, %2;" : "=r"(lp) : "f"(l1), "f"(l0));
    h = hp; l = lp;
}

// ============================================================================
// Kernel 1: feature map (unchanged)
// ============================================================================
__global__ void phi_kernel(const float* __restrict__ x) {
    int warp = (blockIdx.x * blockDim.x + threadIdx.x) >> 5;
    int lane = threadIdx.x & 31;
    if (warp >= B_) return;
    const float* xr = x + (size_t)warp * NSITE;

    float v[8];
    float mn = 3.402823466e38f, mx = -3.402823466e38f;
#pragma unroll
    for (int i = 0; i < 8; i++) {
        v[i] = xr[lane + i * 32];
        mn = fminf(mn, v[i]);
        mx = fmaxf(mx, v[i]);
    }
#pragma unroll
    for (int o = 16; o; o >>= 1) {
        mn = fminf(mn, __shfl_xor_sync(0xffffffffu, mn, o));
        mx = fmaxf(mx, __shfl_xor_sync(0xffffffffu, mx, o));
    }
    float denom = mx - mn + 1e-6f;
#pragma unroll
    for (int i = 0; i < 8; i++) {
        float xn = (v[i] - mn) / denom;
        float s, c;
        sincospif(0.5f * xn, &s, &c);
        int site = lane + i * 32;
        g_cos[(size_t)site * B_ + warp] = c;
        g_sin[(size_t)site * B_ + warp] = s;
    }
}

// ============================================================================
// Kernel 2: split mid into bf16 hi/lo, parity-separated, ldmatrix-tile layout.
// B_par[k=l][n] = mid[step][l][par][n].  Storage per step: 4 k-chunks of 32
// rows; per chunk 4 mats {He,Ho,Le,Lo}; per mat 8x8 tiles stored contiguously:
// el = (ktile_local*16 + ntile)*64 + (k%8)*8 + (n%8).
// ============================================================================
__global__ void split_mid_kernel(const float* __restrict__ mid) {
    int e = blockIdx.x * blockDim.x + threadIdx.x;
    if (e >= NSTEP * 32768) return;
    int rem  = e & 32767;
    int step = e >> 15;
    int l = rem >> 8;            // bond index = GEMM k, 0..127
    int d = (rem >> 7) & 1;      // parity
    int n = rem & 127;
    float v = mid[e];            // mid linear index == e by construction
    __nv_bfloat16 bh = __float2bfloat16(v);
    float fh = __bfloat162float(bh);
    __nv_bfloat16 bl = __float2bfloat16(v - fh);
    int chunk = l >> 5;
    int el = (((l >> 3) & 3) * 16 + (n >> 3)) * 64 + (l & 7) * 8 + (n & 7);
    size_t base = (size_t)step * 65536 + chunk * 16384 + el;
    g_B[base + (size_t)d * 4096]       = bh;   // He / Ho
    g_B[base + (size_t)(2 + d) * 4096] = bl;   // Le / Lo
}

// ============================================================================
// Kernel 3: HMMA MPS chain.  CTA owns 64 samples. Per step:
//   D[64, n, par] += Ah*Bh + Al*Bh + Ah*Bl   (mma.sync m16n8k16 bf16)
//   left' = c*D_e + s*D_o  (register-local: warp owns both parities of its
//   32 n-cols), re-split hi/lo -> stmatrix back to A smem for next step.
// B streamed as 32KB chunks, cp.async triple-buffered ring.
// ============================================================================
__global__ __launch_bounds__(THREADS, 1)
void mps_hmma_kernel(const float* __restrict__ first,
                     const float* __restrict__ last,
                     const float* __restrict__ w,
                     const float* __restrict__ bias,
                     float* __restrict__ out) {
    extern __shared__ __align__(1024) char smem[];
    const uint32_t sb = smem_u32(smem);
    float* cS  = (float*)(smem + SM_CS);
    float* sS  = (float*)(smem + SM_SS);
    float* c2S = (float*)(smem + SM_C2);
    float* s2S = (float*)(smem + SM_S2);
    float* lastS = (float*)(smem + SM_LAST);
    float* red = (float*)(smem + SM_RED);

    const int tid  = threadIdx.x;
    const int lane = tid & 31;
    const int wid  = tid >> 5;
    const int mw   = wid & 1;      // M strip (32 rows)
    const int nw   = wid >> 1;     // N strip (32 n-cols, both parities)
    const int g4   = lane >> 2;    // mma row group 0..7
    const int gA   = lane >> 3;    // ldmatrix lane group 0..3
    const int rowA = lane & 7;     // ldmatrix row-in-tile
    const int b0   = blockIdx.x * BM;

    // stage last tensor (256 floats)
    lastS[tid] = __ldg(&last[tid]);

    // prefetch B chunks 0, 1
#pragma unroll
    for (int qq = 0; qq < 2; ++qq) {
        const char* src = (const char*)g_B + (size_t)qq * 32768;
        uint32_t dst = sb + SM_B + qq * 32768;
#pragma unroll
        for (int c = 0; c < 8; ++c) {
            int idx = tid + c * THREADS;
            cp16(dst + idx * 16, src + (size_t)idx * 16);
        }
        cp_commit();
    }

    // ---- A0 init: left0[r,k] = first[0,k]*c0_r + first[1,k]*s0_r ----
    for (int i = tid; i < BM * D_; i += THREADS) {
        int r = i >> 7, k = i & 127;
        float c0 = __ldg(&g_cos[b0 + r]);
        float s0 = __ldg(&g_sin[b0 + r]);
        float v = __ldg(&first[k]) * c0 + __ldg(&first[D_ + k]) * s0;
        __nv_bfloat16 bh = __float2bfloat16(v);
        float fh = __bfloat162float(bh);
        __nv_bfloat16 bl = __float2bfloat16(v - fh);
        int el = ((r >> 3) * 16 + (k >> 3)) * 64 + (r & 7) * 8 + (k & 7);
        ((__nv_bfloat16*)(smem + SM_AH))[el] = bh;
        ((__nv_bfloat16*)(smem + SM_AL))[el] = bl;
    }
    __syncthreads();

    // ---- site loop ----
    for (int m = 0; m < NSTEP; ++m) {
        float acc[2][2][4][4];   // [par][mt][j n8-tile][4]
#pragma unroll
        for (int p = 0; p < 2; ++p)
#pragma unroll
            for (int t = 0; t < 2; ++t)
#pragma unroll
                for (int j = 0; j < 4; ++j)
#pragma unroll
                    for (int q = 0; q < 4; ++q) acc[p][t][j][q] = 0.0f;

#pragma unroll 1
        for (int kc = 0; kc < 4; ++kc) {
            const int q = m * 4 + kc;
            cp_wait1();
            __syncthreads();   // chunk q visible to all; prior A-writes visible

            if (kc == 0) {     // stage phi for this step's writeback
                if (tid < BM) {
                    cS[tid] = __ldg(&g_cos[(size_t)(m + 1) * B_ + b0 + tid]);
                    sS[tid] = __ldg(&g_sin[(size_t)(m + 1) * B_ + b0 + tid]);
                }
                if (m == NSTEP - 1 && tid >= 64 && tid < 128) {
                    int t = tid - 64;
                    c2S[t] = __ldg(&g_cos[(size_t)(NSITE - 1) * B_ + b0 + t]);
                    s2S[t] = __ldg(&g_sin[(size_t)(NSITE - 1) * B_ + b0 + t]);
                }
            }
            if (q + 2 < TOTQ) {   // prefetch into ring slot (q+2)%3
                const char* src = (const char*)g_B + (size_t)(q + 2) * 32768;
                uint32_t dst = sb + SM_B + ((q + 2) % 3) * 32768;
#pragma unroll
                for (int c = 0; c < 8; ++c) {
                    int idx = tid + c * THREADS;
                    cp16(dst + idx * 16, src + (size_t)idx * 16);
                }
            }
            cp_commit();          // uniform group counting (may be empty)

            const uint32_t bbase = sb + SM_B + (q % 3) * 32768;

#pragma unroll
            for (int c2 = 0; c2 < 2; ++c2) {
                const int kt16 = kc * 2 + c2;
                // A fragments (hi & lo), 2 m-tiles
                uint32_t aH[2][4], aL[2][4];
#pragma unroll
                for (int mt = 0; mt < 2; ++mt) {
                    int MT0 = mw * 4 + mt * 2, KT0 = kt16 * 2;
                    uint32_t off = (uint32_t)(((MT0 + (gA & 1)) * 16 +
                                   (KT0 + (gA >> 1))) * 128 + rowA * 16);
                    ldsm4(aH[mt], sb + SM_AH + off);
                    ldsm4(aL[mt], sb + SM_AL + off);
                }
                // B fragments: 4 mats x 2 n-tile pairs
                uint32_t bf[4][2][4];
                const int ktl0 = c2 * 2;
#pragma unroll
                for (int mat = 0; mat < 4; ++mat)
#pragma unroll
                    for (int p = 0; p < 2; ++p) {
                        int nt0 = nw * 4 + p * 2;
                        uint32_t off = (uint32_t)(mat * 8192 +
                            ((ktl0 + (gA & 1)) * 16 + (nt0 + (gA >> 1))) * 128 +
                            rowA * 16);
                        ldsm4t(bf[mat][p], bbase + off);
                    }
                // 48 HMMA: 2 par x 2 mt x 4 j x 3 products
#pragma unroll
                for (int par = 0; par < 2; ++par)
#pragma unroll
                    for (int mt = 0; mt < 2; ++mt)
#pragma unroll
                        for (int j = 0; j < 4; ++j) {
                            const uint32_t* bh = &bf[par][j >> 1][(j & 1) * 2];
                            const uint32_t* bl = &bf[2 + par][j >> 1][(j & 1) * 2];
                            mma16816(acc[par][mt][j], aH[mt], bh);
                            mma16816(acc[par][mt][j], aL[mt], bh);
                            mma16816(acc[par][mt][j], aH[mt], bl);
                        }
            }
        }

        __syncthreads();   // all HMMA done; cS/sS visible; A smem free to write

        const int rb = mw * 32 + g4;
        if (m < NSTEP - 1) {
            // ---- combine parity + split hi/lo + stmatrix back to A ----
#pragma unroll
            for (int mt = 0; mt < 2; ++mt) {
                float cl = cS[rb + mt * 16], ch = cS[rb + mt * 16 + 8];
                float sl = sS[rb + mt * 16], sh = sS[rb + mt * 16 + 8];
                uint32_t hA[4][2], lA[4][2];
#pragma unroll
                for (int j = 0; j < 4; ++j) {
                    float* E = acc[0][mt][j];
                    float* O = acc[1][mt][j];
                    float r0 = cl * E[0] + sl * O[0];
                    float r1 = cl * E[1] + sl * O[1];
                    float r2 = ch * E[2] + sh * O[2];
                    float r3 = ch * E[3] + sh * O[3];
                    split2(r0, r1, hA[j][0], lA[j][0]);
                    split2(r2, r3, hA[j][1], lA[j][1]);
                }
#pragma unroll
                for (int p = 0; p < 2; ++p) {
                    int MT0 = mw * 4 + mt * 2, KT0 = nw * 4 + p * 2;
                    uint32_t off = (uint32_t)(((MT0 + (gA & 1)) * 16 +
                                   (KT0 + (gA >> 1))) * 128 + rowA * 16);
                    stsm4(sb + SM_AH + off, hA[2 * p][0], hA[2 * p][1],
                          hA[2 * p + 1][0], hA[2 * p + 1][1]);
                    stsm4(sb + SM_AL + off, lA[2 * p][0], lA[2 * p][1],
                          lA[2 * p + 1][0], lA[2 * p + 1][1]);
                }
            }
        } else {
            // ---- final: contract with last site ----
            float part[2][2] = {{0.f, 0.f}, {0.f, 0.f}};  // [mt][rowlo/rowhi]
#pragma unroll
            for (int mt = 0; mt < 2; ++mt) {
                float cl = cS[rb + mt * 16], ch = cS[rb + mt * 16 + 8];
                float sl = sS[rb + mt * 16], sh = sS[rb + mt * 16 + 8];
                float c2l = c2S[rb + mt * 16], c2h = c2S[rb + mt * 16 + 8];
                float s2l = s2S[rb + mt * 16], s2h = s2S[rb + mt * 16 + 8];
#pragma unroll
                for (int j = 0; j < 4; ++j) {
                    float* E = acc[0][mt][j];
                    float* O = acc[1][mt][j];
                    int n0 = nw * 32 + j * 8 + 2 * (lane & 3);
                    float w0l = lastS[2 * n0] * c2l + lastS[2 * n0 + 1] * s2l;
                    float w1l = lastS[2 * n0 + 2] * c2l + lastS[2 * n0 + 3] * s2l;
                    float w0h = lastS[2 * n0] * c2h + lastS[2 * n0 + 1] * s2h;
                    float w1h = lastS[2 * n0 + 2] * c2h + lastS[2 * n0 + 3] * s2h;
                    part[mt][0] += (cl * E[0] + sl * O[0]) * w0l
                                 + (cl * E[1] + sl * O[1]) * w1l;
                    part[mt][1] += (ch * E[2] + sh * O[2]) * w0h
                                 + (ch * E[3] + sh * O[3]) * w1h;
                }
            }
            // quad reduce (lanes 4g..4g+3 share rows)
#pragma unroll
            for (int o = 1; o <= 2; o <<= 1) {
                part[0][0] += __shfl_xor_sync(0xffffffffu, part[0][0], o);
                part[0][1] += __shfl_xor_sync(0xffffffffu, part[0][1], o);
                part[1][0] += __shfl_xor_sync(0xffffffffu, part[1][0], o);
                part[1][1] += __shfl_xor_sync(0xffffffffu, part[1][1], o);
            }
            if ((lane & 3) == 0) {
                red[nw * 64 + rb]      = part[0][0];
                red[nw * 64 + rb + 8]  = part[0][1];
                red[nw * 64 + rb + 16] = part[1][0];
                red[nw * 64 + rb + 24] = part[1][1];
            }
            __syncthreads();
            if (tid < BM) {
                float tot = red[tid] + red[64 + tid] + red[128 + tid]
                          + red[192 + tid];
#pragma unroll
                for (int o = 0; o < OUT_; ++o)
                    out[(size_t)(b0 + tid) * OUT_ + o] =
                        tot * __ldg(&w[o]) + __ldg(&bias[o]);
            }
        }
    }
}

// ============================================================================
// Launch: 3 kernels.
// ============================================================================
extern "C" void kernel_launch(void* const* d_in, const int* in_sizes, int n_in,
                              void* d_out, int out_size) {
    const float* x     = (const float*)d_in[0];  // [B, N]
    const float* first = (const float*)d_in[1];  // [1, 2, D]
    const float* mid   = (const float*)d_in[2];  // [N-2, D, 2, D]
    const float* last  = (const float*)d_in[3];  // [D, 2, 1]
    const float* w     = (const float*)d_in[4];  // [OUT, 1]
    const float* bias  = (const float*)d_in[5];  // [OUT]
    float* out = (float*)d_out;                  // [B, OUT]

    cudaFuncSetAttribute(mps_hmma_kernel,
                         cudaFuncAttributeMaxDynamicSharedMemorySize,
                         SMEM_TOTAL);

    phi_kernel<<<B_ / 8, 256>>>(x);
    split_mid_kernel<<<(NSTEP * 32768 + 255) / 256, 256>>>(mid);
    mps_hmma_kernel<<<NCTA, THREADS, SMEM_TOTAL>>>(first, last, w, bias, out);
}

// round 7
// speedup vs baseline: 7.5860x; 1.0004x over previous
#include <cuda_runtime.h>
#include <cuda_bf16.h>
#include <cstdint>

// Problem constants
#define B_     8192
#define NSITE  256
#define D_     128
#define OUT_   10
#define NSTEP  254
#define BM     64            // samples per CTA
#define NCTA   (B_ / BM)     // 128 CTAs
#define THREADS 256          // 8 warps
#define TOTQ   (NSTEP * 4)   // total 32KB B-chunks streamed

// smem byte offsets
#define SM_AH   0            // A-hi bf16 tiles: 64x128 -> 16 KB
#define SM_AL   16384        // A-lo
#define SM_B    32768        // 3 x 32768 B-chunk ring
#define SM_CS   131072       // cos site m+1 [64]
#define SM_SS   131328
#define SM_C2   131584       // cos site 255 [64]
#define SM_S2   131840
#define SM_LAST 132096       // last tensor staged [256]
#define SM_RED  133120       // final reduce [4][64]
#define SMEM_TOTAL 134144

// Scratch globals
__device__ float g_cos[NSITE * B_];                      // 8 MB
__device__ float g_sin[NSITE * B_];                      // 8 MB
// Pre-split B: [step][chunk(4)][mat{He,Ho,Le,Lo}][4096 bf16 tile-contiguous]
__device__ __nv_bfloat16 g_B[(size_t)NSTEP * 65536];     // 33.3 MB

// ---------------------------------------------------------------------------
// Base-ISA asm helpers
// ---------------------------------------------------------------------------
__device__ __forceinline__ uint32_t smem_u32(const void* p) {
    uint32_t a;
    asm("{ .reg .u64 t; cvta.to.shared.u64 t, %1; cvt.u32.u64 %0, t; }"
        : "=r"(a) : "l"(p));
    return a;
}
__device__ __forceinline__ void cp16(uint32_t dst, const void* src) {
    asm volatile("cp.async.cg.shared.global [%0], [%1], 16;" :: "r"(dst), "l"(src));
}
__device__ __forceinline__ void cp_commit() {
    asm volatile("cp.async.commit_group;" ::: "memory");
}
__device__ __forceinline__ void cp_wait1() {
    asm volatile("cp.async.wait_group 1;" ::: "memory");
}
__device__ __forceinline__ void ldsm4(uint32_t* r, uint32_t a) {
    asm volatile("ldmatrix.sync.aligned.m8n8.x4.shared.b16 {%0,%1,%2,%3}, [%4];"
                 : "=r"(r[0]), "=r"(r[1]), "=r"(r[2]), "=r"(r[3]) : "r"(a));
}
__device__ __forceinline__ void ldsm4t(uint32_t* r, uint32_t a) {
    asm volatile("ldmatrix.sync.aligned.m8n8.x4.trans.shared.b16 {%0,%1,%2,%3}, [%4];"
                 : "=r"(r[0]), "=r"(r[1]), "=r"(r[2]), "=r"(r[3]) : "r"(a));
}
__device__ __forceinline__ void stsm4(uint32_t a, uint32_t r0, uint32_t r1,
                                      uint32_t r2, uint32_t r3) {
    asm volatile("stmatrix.sync.aligned.m8n8.x4.shared.b16 [%0], {%1,%2,%3,%4};"
                 :: "r"(a), "r"(r0), "r"(r1), "r"(r2), "r"(r3) : "memory");
}
__device__ __forceinline__ void mma16816(float* c, const uint32_t* a,
                                         const uint32_t* b) {
    asm volatile(
        "mma.sync.aligned.m16n8k16.row.col.f32.bf16.bf16.f32 "
        "{%0,%1,%2,%3}, {%4,%5,%6,%7}, {%8,%9}, {%0,%1,%2,%3};"
        : "+f"(c[0]), "+f"(c[1]), "+f"(c[2]), "+f"(c[3])
        : "r"(a[0]), "r"(a[1]), "r"(a[2]), "r"(a[3]), "r"(b[0]), "r"(b[1]));
}
// hi/lo bf16 split of (r0, r1) -> packed bf16x2 (low half = r0)
__device__ __forceinline__ void split2(float r0, float r1,
                                       uint32_t& h, uint32_t& l) {
    uint32_t hp;
    asm("cvt.rn.satfinite.bf16x2.f32 %0, %1, %2;" : "=r"(hp) : "f"(r1), "f"(r0));
    float f0 = __uint_as_float(hp << 16);
    float f1 = __uint_as_float(hp & 0xFFFF0000u);
    float l0 = r0 - f0, l1 = r1 - f1;
    uint32_t lp;
    asm("cvt.rn.satfinite.bf16x2.f32 %0, %1, %2;" : "=r"(lp) : "f"(l1), "f"(l0));
    h = hp; l = lp;
}

// ============================================================================
// Kernel 1: feature map. MUFU-based sin/cos (error ~2^-21, negligible vs the
// 1.3e-4 chain error).
// ============================================================================
__global__ void phi_kernel(const float* __restrict__ x) {
    int warp = (blockIdx.x * blockDim.x + threadIdx.x) >> 5;
    int lane = threadIdx.x & 31;
    if (warp >= B_) return;
    const float* xr = x + (size_t)warp * NSITE;

    float v[8];
    float mn = 3.402823466e38f, mx = -3.402823466e38f;
#pragma unroll
    for (int i = 0; i < 8; i++) {
        v[i] = xr[lane + i * 32];
        mn = fminf(mn, v[i]);
        mx = fmaxf(mx, v[i]);
    }
#pragma unroll
    for (int o = 16; o; o >>= 1) {
        mn = fminf(mn, __shfl_xor_sync(0xffffffffu, mn, o));
        mx = fmaxf(mx, __shfl_xor_sync(0xffffffffu, mx, o));
    }
    float inv = 1.0f / (mx - mn + 1e-6f);
#pragma unroll
    for (int i = 0; i < 8; i++) {
        float ang = 1.57079632679f * ((v[i] - mn) * inv);
        float s, c;
        __sincosf(ang, &s, &c);
        int site = lane + i * 32;
        g_cos[(size_t)site * B_ + warp] = c;
        g_sin[(size_t)site * B_ + warp] = s;
    }
}

// ============================================================================
// Kernel 2: split mid into bf16 hi/lo, parity-separated, ldmatrix-tile layout.
// ============================================================================
__global__ void split_mid_kernel(const float* __restrict__ mid) {
    int e = blockIdx.x * blockDim.x + threadIdx.x;
    if (e >= NSTEP * 32768) return;
    int rem  = e & 32767;
    int step = e >> 15;
    int l = rem >> 8;            // bond index = GEMM k, 0..127
    int d = (rem >> 7) & 1;      // parity
    int n = rem & 127;
    float v = mid[e];
    __nv_bfloat16 bh = __float2bfloat16(v);
    float fh = __bfloat162float(bh);
    __nv_bfloat16 bl = __float2bfloat16(v - fh);
    int chunk = l >> 5;
    int el = (((l >> 3) & 3) * 16 + (n >> 3)) * 64 + (l & 7) * 8 + (n & 7);
    size_t base = (size_t)step * 65536 + chunk * 16384 + el;
    g_B[base + (size_t)d * 4096]       = bh;   // He / Ho
    g_B[base + (size_t)(2 + d) * 4096] = bl;   // Le / Lo
}

// ============================================================================
// Kernel 3: HMMA MPS chain. Product-major MMA issue: each of the 16
// accumulators is re-touched at distance 16 MMAs -> no RAW stalls on the
// tensor pipe.
// ============================================================================
__global__ __launch_bounds__(THREADS, 1)
void mps_hmma_kernel(const float* __restrict__ first,
                     const float* __restrict__ last,
                     const float* __restrict__ w,
                     const float* __restrict__ bias,
                     float* __restrict__ out) {
    extern __shared__ __align__(1024) char smem[];
    const uint32_t sb = smem_u32(smem);
    float* cS  = (float*)(smem + SM_CS);
    float* sS  = (float*)(smem + SM_SS);
    float* c2S = (float*)(smem + SM_C2);
    float* s2S = (float*)(smem + SM_S2);
    float* lastS = (float*)(smem + SM_LAST);
    float* red = (float*)(smem + SM_RED);

    const int tid  = threadIdx.x;
    const int lane = tid & 31;
    const int wid  = tid >> 5;
    const int mw   = wid & 1;      // M strip (32 rows)
    const int nw   = wid >> 1;     // N strip (32 n-cols, both parities)
    const int g4   = lane >> 2;    // mma row group 0..7
    const int gA   = lane >> 3;    // ldmatrix lane group 0..3
    const int rowA = lane & 7;     // ldmatrix row-in-tile
    const int b0   = blockIdx.x * BM;

    lastS[tid] = __ldg(&last[tid]);

    // prefetch B chunks 0, 1
#pragma unroll
    for (int qq = 0; qq < 2; ++qq) {
        const char* src = (const char*)g_B + (size_t)qq * 32768;
        uint32_t dst = sb + SM_B + qq * 32768;
#pragma unroll
        for (int c = 0; c < 8; ++c) {
            int idx = tid + c * THREADS;
            cp16(dst + idx * 16, src + (size_t)idx * 16);
        }
        cp_commit();
    }

    // ---- A0 init ----
    for (int i = tid; i < BM * D_; i += THREADS) {
        int r = i >> 7, k = i & 127;
        float c0 = __ldg(&g_cos[b0 + r]);
        float s0 = __ldg(&g_sin[b0 + r]);
        float v = __ldg(&first[k]) * c0 + __ldg(&first[D_ + k]) * s0;
        __nv_bfloat16 bh = __float2bfloat16(v);
        float fh = __bfloat162float(bh);
        __nv_bfloat16 bl = __float2bfloat16(v - fh);
        int el = ((r >> 3) * 16 + (k >> 3)) * 64 + (r & 7) * 8 + (k & 7);
        ((__nv_bfloat16*)(smem + SM_AH))[el] = bh;
        ((__nv_bfloat16*)(smem + SM_AL))[el] = bl;
    }
    __syncthreads();

    // ---- site loop ----
    for (int m = 0; m < NSTEP; ++m) {
        float acc[2][2][4][4];   // [par][mt][j n8-tile][4]
#pragma unroll
        for (int p = 0; p < 2; ++p)
#pragma unroll
            for (int t = 0; t < 2; ++t)
#pragma unroll
                for (int j = 0; j < 4; ++j)
#pragma unroll
                    for (int q = 0; q < 4; ++q) acc[p][t][j][q] = 0.0f;

#pragma unroll 1
        for (int kc = 0; kc < 4; ++kc) {
            const int q = m * 4 + kc;
            cp_wait1();
            __syncthreads();   // chunk q visible; prior A-writes visible

            if (kc == 0) {     // stage phi for this step's writeback
                if (tid < BM) {
                    cS[tid] = __ldg(&g_cos[(size_t)(m + 1) * B_ + b0 + tid]);
                    sS[tid] = __ldg(&g_sin[(size_t)(m + 1) * B_ + b0 + tid]);
                }
                if (m == NSTEP - 1 && tid >= 64 && tid < 128) {
                    int t = tid - 64;
                    c2S[t] = __ldg(&g_cos[(size_t)(NSITE - 1) * B_ + b0 + t]);
                    s2S[t] = __ldg(&g_sin[(size_t)(NSITE - 1) * B_ + b0 + t]);
                }
            }
            if (q + 2 < TOTQ) {   // prefetch into ring slot (q+2)%3
                const char* src = (const char*)g_B + (size_t)(q + 2) * 32768;
                uint32_t dst = sb + SM_B + ((q + 2) % 3) * 32768;
#pragma unroll
                for (int c = 0; c < 8; ++c) {
                    int idx = tid + c * THREADS;
                    cp16(dst + idx * 16, src + (size_t)idx * 16);
                }
            }
            cp_commit();          // uniform group counting (may be empty)

            const uint32_t bbase = sb + SM_B + (q % 3) * 32768;

#pragma unroll
            for (int c2 = 0; c2 < 2; ++c2) {
                const int kt16 = kc * 2 + c2;
                uint32_t aH[2][4], aL[2][4];
#pragma unroll
                for (int mt = 0; mt < 2; ++mt) {
                    int MT0 = mw * 4 + mt * 2, KT0 = kt16 * 2;
                    uint32_t off = (uint32_t)(((MT0 + (gA & 1)) * 16 +
                                   (KT0 + (gA >> 1))) * 128 + rowA * 16);
                    ldsm4(aH[mt], sb + SM_AH + off);
                    ldsm4(aL[mt], sb + SM_AL + off);
                }
                uint32_t bf[4][2][4];
                const int ktl0 = c2 * 2;
#pragma unroll
                for (int mat = 0; mat < 4; ++mat)
#pragma unroll
                    for (int p = 0; p < 2; ++p) {
                        int nt0 = nw * 4 + p * 2;
                        uint32_t off = (uint32_t)(mat * 8192 +
                            ((ktl0 + (gA & 1)) * 16 + (nt0 + (gA >> 1))) * 128 +
                            rowA * 16);
                        ldsm4t(bf[mat][p], bbase + off);
                    }
                // 48 HMMA, PRODUCT-MAJOR: 16 independent acc targets per
                // product; each acc reused at distance 16 -> no RAW stalls.
#define MMA_SWEEP(AM, MB)                                                    \
                _Pragma("unroll")                                            \
                for (int par = 0; par < 2; ++par)                            \
                    _Pragma("unroll")                                        \
                    for (int mt = 0; mt < 2; ++mt)                           \
                        _Pragma("unroll")                                    \
                        for (int j = 0; j < 4; ++j)                          \
                            mma16816(acc[par][mt][j], AM[mt],                \
                                     &bf[(MB) + par][j >> 1][(j & 1) * 2]);
                MMA_SWEEP(aH, 0)   // Ah * Bh
                MMA_SWEEP(aL, 0)   // Al * Bh
                MMA_SWEEP(aH, 2)   // Ah * Bl
#undef MMA_SWEEP
            }
        }

        __syncthreads();   // all HMMA done; cS/sS visible; A smem writable

        const int rb = mw * 32 + g4;
        if (m < NSTEP - 1) {
            // ---- combine parity + split hi/lo + stmatrix back to A ----
#pragma unroll
            for (int mt = 0; mt < 2; ++mt) {
                float cl = cS[rb + mt * 16], ch = cS[rb + mt * 16 + 8];
                float sl = sS[rb + mt * 16], sh = sS[rb + mt * 16 + 8];
                uint32_t hA[4][2], lA[4][2];
#pragma unroll
                for (int j = 0; j < 4; ++j) {
                    float* E = acc[0][mt][j];
                    float* O = acc[1][mt][j];
                    float r0 = cl * E[0] + sl * O[0];
                    float r1 = cl * E[1] + sl * O[1];
                    float r2 = ch * E[2] + sh * O[2];
                    float r3 = ch * E[3] + sh * O[3];
                    split2(r0, r1, hA[j][0], lA[j][0]);
                    split2(r2, r3, hA[j][1], lA[j][1]);
                }
#pragma unroll
                for (int p = 0; p < 2; ++p) {
                    int MT0 = mw * 4 + mt * 2, KT0 = nw * 4 + p * 2;
                    uint32_t off = (uint32_t)(((MT0 + (gA & 1)) * 16 +
                                   (KT0 + (gA >> 1))) * 128 + rowA * 16);
                    stsm4(sb + SM_AH + off, hA[2 * p][0], hA[2 * p][1],
                          hA[2 * p + 1][0], hA[2 * p + 1][1]);
                    stsm4(sb + SM_AL + off, lA[2 * p][0], lA[2 * p][1],
                          lA[2 * p + 1][0], lA[2 * p + 1][1]);
                }
            }
        } else {
            // ---- final: contract with last site ----
            float part[2][2] = {{0.f, 0.f}, {0.f, 0.f}};
#pragma unroll
            for (int mt = 0; mt < 2; ++mt) {
                float cl = cS[rb + mt * 16], ch = cS[rb + mt * 16 + 8];
                float sl = sS[rb + mt * 16], sh = sS[rb + mt * 16 + 8];
                float c2l = c2S[rb + mt * 16], c2h = c2S[rb + mt * 16 + 8];
                float s2l = s2S[rb + mt * 16], s2h = s2S[rb + mt * 16 + 8];
#pragma unroll
                for (int j = 0; j < 4; ++j) {
                    float* E = acc[0][mt][j];
                    float* O = acc[1][mt][j];
                    int n0 = nw * 32 + j * 8 + 2 * (lane & 3);
                    float w0l = lastS[2 * n0] * c2l + lastS[2 * n0 + 1] * s2l;
                    float w1l = lastS[2 * n0 + 2] * c2l + lastS[2 * n0 + 3] * s2l;
                    float w0h = lastS[2 * n0] * c2h + lastS[2 * n0 + 1] * s2h;
                    float w1h = lastS[2 * n0 + 2] * c2h + lastS[2 * n0 + 3] * s2h;
                    part[mt][0] += (cl * E[0] + sl * O[0]) * w0l
                                 + (cl * E[1] + sl * O[1]) * w1l;
                    part[mt][1] += (ch * E[2] + sh * O[2]) * w0h
                                 + (ch * E[3] + sh * O[3]) * w1h;
                }
            }
#pragma unroll
            for (int o = 1; o <= 2; o <<= 1) {
                part[0][0] += __shfl_xor_sync(0xffffffffu, part[0][0], o);
                part[0][1] += __shfl_xor_sync(0xffffffffu, part[0][1], o);
                part[1][0] += __shfl_xor_sync(0xffffffffu, part[1][0], o);
                part[1][1] += __shfl_xor_sync(0xffffffffu, part[1][1], o);
            }
            if ((lane & 3) == 0) {
                red[nw * 64 + rb]      = part[0][0];
                red[nw * 64 + rb + 8]  = part[0][1];
                red[nw * 64 + rb + 16] = part[1][0];
                red[nw * 64 + rb + 24] = part[1][1];
            }
            __syncthreads();
            if (tid < BM) {
                float tot = red[tid] + red[64 + tid] + red[128 + tid]
                          + red[192 + tid];
#pragma unroll
                for (int o = 0; o < OUT_; ++o)
                    out[(size_t)(b0 + tid) * OUT_ + o] =
                        tot * __ldg(&w[o]) + __ldg(&bias[o]);
            }
        }
    }
}

// ============================================================================
// Launch: 3 kernels.
// ============================================================================
extern "C" void kernel_launch(void* const* d_in, const int* in_sizes, int n_in,
                              void* d_out, int out_size) {
    const float* x     = (const float*)d_in[0];  // [B, N]
    const float* first = (const float*)d_in[1];  // [1, 2, D]
    const float* mid   = (const float*)d_in[2];  // [N-2, D, 2, D]
    const float* last  = (const float*)d_in[3];  // [D, 2, 1]
    const float* w     = (const float*)d_in[4];  // [OUT, 1]
    const float* bias  = (const float*)d_in[5];  // [OUT]
    float* out = (float*)d_out;                  // [B, OUT]

    cudaFuncSetAttribute(mps_hmma_kernel,
                         cudaFuncAttributeMaxDynamicSharedMemorySize,
                         SMEM_TOTAL);

    phi_kernel<<<B_ / 8, 256>>>(x);
    split_mid_kernel<<<(NSTEP * 32768 + 255) / 256, 256>>>(mid);
    mps_hmma_kernel<<<NCTA, THREADS, SMEM_TOTAL>>>(first, last, w, bias, out);
}

// round 8
// speedup vs baseline: 7.9880x; 1.0530x over previous
#include <cuda_runtime.h>
#include <cuda_bf16.h>
#include <cstdint>

// Problem constants
#define B_     8192
#define NSITE  256
#define D_     128
#define OUT_   10
#define NSTEP  254
#define BM     64            // samples per CTA
#define NCTA   (B_ / BM)     // 128 CTAs
#define THREADS 256          // 8 warps, N-split only

// smem byte offsets (static smem, 36 KB)
#define SM_AH   0            // A-hi bf16 tiles: 64x128 -> 16 KB
#define SM_AL   16384        // A-lo
#define SM_CS   32768        // cos site m+1 [64]
#define SM_SS   33024
#define SM_C2   33280        // cos site 255 [64]
#define SM_S2   33536
#define SM_LAST 33792        // last tensor staged [256 floats]
#define SM_RED  34816        // final reduce [8][64]
#define SMEM_TOTAL 36864

// Scratch globals
__device__ float g_cos[NSITE * B_];                      // 8 MB
__device__ float g_sin[NSITE * B_];                      // 8 MB
// Fragment-major pre-split B: per step 128KB laid out as
// [c2:8][warp:8][ldg:4][lane:32][16B]  (ldg f>>1 holds fragment sets 2i,2i+1;
// set f = mat*4 + parity*2 + n8; within reg: b0/b1 = k<8 / k>=8)
__device__ __nv_bfloat16 g_B[(size_t)NSTEP * 65536];     // 33.3 MB

// ---------------------------------------------------------------------------
// Base-ISA asm helpers
// ---------------------------------------------------------------------------
__device__ __forceinline__ uint32_t smem_u32(const void* p) {
    uint32_t a;
    asm("{ .reg .u64 t; cvta.to.shared.u64 t, %1; cvt.u32.u64 %0, t; }"
        : "=r"(a) : "l"(p));
    return a;
}
__device__ __forceinline__ void ldsm4(uint32_t* r, uint32_t a) {
    asm volatile("ldmatrix.sync.aligned.m8n8.x4.shared.b16 {%0,%1,%2,%3}, [%4];"
                 : "=r"(r[0]), "=r"(r[1]), "=r"(r[2]), "=r"(r[3]) : "r"(a));
}
__device__ __forceinline__ void stsm4(uint32_t a, uint32_t r0, uint32_t r1,
                                      uint32_t r2, uint32_t r3) {
    asm volatile("stmatrix.sync.aligned.m8n8.x4.shared.b16 [%0], {%1,%2,%3,%4};"
                 :: "r"(a), "r"(r0), "r"(r1), "r"(r2), "r"(r3) : "memory");
}
__device__ __forceinline__ void mma16816(float* c, const uint32_t* a,
                                         const uint32_t* b) {
    asm volatile(
        "mma.sync.aligned.m16n8k16.row.col.f32.bf16.bf16.f32 "
        "{%0,%1,%2,%3}, {%4,%5,%6,%7}, {%8,%9}, {%0,%1,%2,%3};"
        : "+f"(c[0]), "+f"(c[1]), "+f"(c[2]), "+f"(c[3])
        : "r"(a[0]), "r"(a[1]), "r"(a[2]), "r"(a[3]), "r"(b[0]), "r"(b[1]));
}
// hi/lo bf16 split of (r0, r1) -> packed bf16x2 (low half = r0)
__device__ __forceinline__ void split2(float r0, float r1,
                                       uint32_t& h, uint32_t& l) {
    uint32_t hp;
    asm("cvt.rn.satfinite.bf16x2.f32 %0, %1, %2;" : "=r"(hp) : "f"(r1), "f"(r0));
    float f0 = __uint_as_float(hp << 16);
    float f1 = __uint_as_float(hp & 0xFFFF0000u);
    float l0 = r0 - f0, l1 = r1 - f1;
    uint32_t lp;
    asm("cvt.rn.satfinite.bf16x2.f32 %0, %1, %2;" : "=r"(lp) : "f"(l1), "f"(l0));
    h = hp; l = lp;
}

// ============================================================================
// Kernel 1: feature map (MUFU sincos)
// ============================================================================
__global__ void phi_kernel(const float* __restrict__ x) {
    int warp = (blockIdx.x * blockDim.x + threadIdx.x) >> 5;
    int lane = threadIdx.x & 31;
    if (warp >= B_) return;
    const float* xr = x + (size_t)warp * NSITE;

    float v[8];
    float mn = 3.402823466e38f, mx = -3.402823466e38f;
#pragma unroll
    for (int i = 0; i < 8; i++) {
        v[i] = xr[lane + i * 32];
        mn = fminf(mn, v[i]);
        mx = fmaxf(mx, v[i]);
    }
#pragma unroll
    for (int o = 16; o; o >>= 1) {
        mn = fminf(mn, __shfl_xor_sync(0xffffffffu, mn, o));
        mx = fmaxf(mx, __shfl_xor_sync(0xffffffffu, mx, o));
    }
    float inv = 1.0f / (mx - mn + 1e-6f);
#pragma unroll
    for (int i = 0; i < 8; i++) {
        float ang = 1.57079632679f * ((v[i] - mn) * inv);
        float s, c;
        __sincosf(ang, &s, &c);
        int site = lane + i * 32;
        g_cos[(size_t)site * B_ + warp] = c;
        g_sin[(size_t)site * B_ + warp] = s;
    }
}

// ============================================================================
// Kernel 2: split mid into bf16 hi/lo, FRAGMENT-MAJOR layout (see g_B doc).
// ============================================================================
__global__ void split_mid_kernel(const float* __restrict__ mid) {
    int e = blockIdx.x * blockDim.x + threadIdx.x;
    if (e >= NSTEP * 32768) return;
    int step = e >> 15;
    int rem  = e & 32767;
    int l = rem >> 8;            // bond index = GEMM k, 0..127
    int d = (rem >> 7) & 1;      // parity
    int n = rem & 127;
    float v = mid[e];
    __nv_bfloat16 bh = __float2bfloat16(v);
    float fh = __bfloat162float(bh);
    __nv_bfloat16 bl = __float2bfloat16(v - fh);

    int c2 = l >> 4, kl = l & 15;
    int w  = n >> 4, n8 = (n >> 3) & 1, nn = n & 7;
    int lane  = (nn << 2) | ((kl >> 1) & 3);
    int reg_k = (kl >> 3) & 1;          // b0 / b1
    int half  = kl & 1;                 // low/high bf16 in u32
    size_t base = (size_t)step * 65536 + (size_t)((c2 * 8 + w) * 4) * 256;
#pragma unroll
    for (int mat = 0; mat < 2; ++mat) {
        int f = mat * 4 + d * 2 + n8;
        size_t idx = base + (size_t)(f >> 1) * 256 + lane * 8
                   + ((f & 1) * 2 + reg_k) * 2 + half;
        g_B[idx] = mat ? bl : bh;
    }
}

// ============================================================================
// Kernel 3: HMMA MPS chain, B streamed L2->registers (no smem for B).
// Warp w owns phys n-cols [w*16, w*16+16), both parities. Per k-chunk (c2):
// 4 LDG.128/thread (register double-buffered, pipelined 1 chunk ahead),
// 8 ldsm4 for A (hi/lo), 48 MMA. Epilogue: parity-combine + hi/lo split +
// stmatrix back to A smem.
// ============================================================================
__global__ __launch_bounds__(THREADS, 1)
void mps_hmma_kernel(const float* __restrict__ first,
                     const float* __restrict__ last,
                     const float* __restrict__ w,
                     const float* __restrict__ bias,
                     float* __restrict__ out) {
    __shared__ __align__(1024) char smem[SMEM_TOTAL];
    const uint32_t sb = smem_u32(smem);
    float* cS    = (float*)(smem + SM_CS);
    float* sS    = (float*)(smem + SM_SS);
    float* c2S   = (float*)(smem + SM_C2);
    float* s2S   = (float*)(smem + SM_S2);
    float* lastS = (float*)(smem + SM_LAST);
    float* red   = (float*)(smem + SM_RED);

    const int tid  = threadIdx.x;
    const int lane = tid & 31;
    const int wd   = tid >> 5;     // warp = n-strip 0..7 (16 phys cols)
    const int gA   = lane >> 3;    // ldmatrix tile group
    const int rowA = lane & 7;
    const int g4   = lane >> 2;    // mma row-in-tile
    const int q4   = lane & 3;
    const int b0   = blockIdx.x * BM;

    lastS[tid] = __ldg(&last[tid]);

    // ---- A0 init ----
    for (int i = tid; i < BM * D_; i += THREADS) {
        int r = i >> 7, k = i & 127;
        float c0 = __ldg(&g_cos[b0 + r]);
        float s0 = __ldg(&g_sin[b0 + r]);
        float v = __ldg(&first[k]) * c0 + __ldg(&first[D_ + k]) * s0;
        __nv_bfloat16 bh = __float2bfloat16(v);
        float fh = __bfloat162float(bh);
        __nv_bfloat16 bl = __float2bfloat16(v - fh);
        int el = ((r >> 3) * 16 + (k >> 3)) * 64 + (r & 7) * 8 + (k & 7);
        ((__nv_bfloat16*)(smem + SM_AH))[el] = bh;
        ((__nv_bfloat16*)(smem + SM_AL))[el] = bl;
    }

    uint4 Bb0[4], Bb1[4];

#define LOADB(R, step_, c2_) do {                                            \
    const uint4* _p = (const uint4*)(g_B + (size_t)(step_) * 65536)          \
                    + ((c2_) * 8 + wd) * 128 + lane;                         \
    R[0] = __ldg(_p); R[1] = __ldg(_p + 32);                                 \
    R[2] = __ldg(_p + 64); R[3] = __ldg(_p + 96);                            \
} while (0)

    LOADB(Bb0, 0, 0);
    __syncthreads();

#define SWEEP(AF, MB, CUR)                                                   \
    _Pragma("unroll") for (int mt = 0; mt < 4; ++mt)                         \
    _Pragma("unroll") for (int d2 = 0; d2 < 2; ++d2)                         \
    _Pragma("unroll") for (int n8 = 0; n8 < 2; ++n8) {                       \
        const int f = (MB) + d2 * 2 + n8;                                    \
        mma16816(acc[mt][d2][n8], AF[mt],                                    \
                 (const uint32_t*)&CUR[f >> 1] + (f & 1) * 2);               \
    }

#define BODY(c2v, CUR, NXT) {                                                \
    if ((c2v) < 7)            LOADB(NXT, m, (c2v) + 1);                      \
    else if (m < NSTEP - 1)   LOADB(NXT, m + 1, 0);                          \
    if ((c2v) == 0) {                                                        \
        if (tid < BM) {                                                      \
            cS[tid] = __ldg(&g_cos[(size_t)(m + 1) * B_ + b0 + tid]);        \
            sS[tid] = __ldg(&g_sin[(size_t)(m + 1) * B_ + b0 + tid]);        \
        }                                                                    \
        if (m == NSTEP - 1 && tid >= 64 && tid < 128) {                      \
            int t = tid - 64;                                                \
            c2S[t] = __ldg(&g_cos[(size_t)(NSITE - 1) * B_ + b0 + t]);       \
            s2S[t] = __ldg(&g_sin[(size_t)(NSITE - 1) * B_ + b0 + t]);       \
        }                                                                    \
    }                                                                        \
    uint32_t aH[4][4], aL[4][4];                                             \
    _Pragma("unroll") for (int mt = 0; mt < 4; ++mt) {                       \
        uint32_t off = (uint32_t)(((mt * 2 + (gA & 1)) * 16 +                \
                       ((c2v) * 2 + (gA >> 1))) * 128 + rowA * 16);          \
        ldsm4(aH[mt], sb + SM_AH + off);                                     \
        ldsm4(aL[mt], sb + SM_AL + off);                                     \
    }                                                                        \
    SWEEP(aH, 0, CUR)   /* Ah*Bh */                                          \
    SWEEP(aL, 0, CUR)   /* Al*Bh */                                          \
    SWEEP(aH, 4, CUR)   /* Ah*Bl */                                          \
}

    // ---- site loop ----
#pragma unroll 1
    for (int m = 0; m < NSTEP; ++m) {
        __syncthreads();   // prev epilogue stsm visible before ldsm

        float acc[4][2][2][4];   // [mt][parity][n8][quad]
#pragma unroll
        for (int mt = 0; mt < 4; ++mt)
#pragma unroll
            for (int d2 = 0; d2 < 2; ++d2)
#pragma unroll
                for (int n8 = 0; n8 < 2; ++n8)
#pragma unroll
                    for (int q = 0; q < 4; ++q) acc[mt][d2][n8][q] = 0.0f;

#pragma unroll
        for (int cp = 0; cp < 4; ++cp) {
            BODY(2 * cp,     Bb0, Bb1)
            BODY(2 * cp + 1, Bb1, Bb0)
        }

        __syncthreads();   // all A ldsm reads done before overwrite

        if (m < NSTEP - 1) {
            // ---- epilogue: combine parity, split hi/lo, stsm to A ----
#pragma unroll
            for (int mt = 0; mt < 4; ++mt) {
                float cl = cS[mt * 16 + g4], ch = cS[mt * 16 + g4 + 8];
                float sl = sS[mt * 16 + g4], sh = sS[mt * 16 + g4 + 8];
                uint32_t hA[2][2], lA[2][2];
#pragma unroll
                for (int n8 = 0; n8 < 2; ++n8) {
                    float* E = acc[mt][0][n8];
                    float* O = acc[mt][1][n8];
                    float v0 = cl * E[0] + sl * O[0];
                    float v1 = cl * E[1] + sl * O[1];
                    float v2 = ch * E[2] + sh * O[2];
                    float v3 = ch * E[3] + sh * O[3];
                    split2(v0, v1, hA[n8][0], lA[n8][0]);
                    split2(v2, v3, hA[n8][1], lA[n8][1]);
                }
                uint32_t off = (uint32_t)(((mt * 2 + (gA & 1)) * 16 +
                               (wd * 2 + (gA >> 1))) * 128 + rowA * 16);
                stsm4(sb + SM_AH + off, hA[0][0], hA[0][1], hA[1][0], hA[1][1]);
                stsm4(sb + SM_AL + off, lA[0][0], lA[0][1], lA[1][0], lA[1][1]);
            }
        } else {
            // ---- final: contract with last site + linear head ----
            float part[4][2];
#pragma unroll
            for (int mt = 0; mt < 4; ++mt) { part[mt][0] = 0.f; part[mt][1] = 0.f; }
#pragma unroll
            for (int mt = 0; mt < 4; ++mt) {
                float cl = cS[mt * 16 + g4], ch = cS[mt * 16 + g4 + 8];
                float sl = sS[mt * 16 + g4], sh = sS[mt * 16 + g4 + 8];
                float c2l = c2S[mt * 16 + g4], c2h = c2S[mt * 16 + g4 + 8];
                float s2l = s2S[mt * 16 + g4], s2h = s2S[mt * 16 + g4 + 8];
#pragma unroll
                for (int n8 = 0; n8 < 2; ++n8) {
                    float* E = acc[mt][0][n8];
                    float* O = acc[mt][1][n8];
                    int n0 = wd * 16 + n8 * 8 + 2 * q4;
                    float w0l = lastS[2 * n0] * c2l + lastS[2 * n0 + 1] * s2l;
                    float w1l = lastS[2 * n0 + 2] * c2l + lastS[2 * n0 + 3] * s2l;
                    float w0h = lastS[2 * n0] * c2h + lastS[2 * n0 + 1] * s2h;
                    float w1h = lastS[2 * n0 + 2] * c2h + lastS[2 * n0 + 3] * s2h;
                    part[mt][0] += (cl * E[0] + sl * O[0]) * w0l
                                 + (cl * E[1] + sl * O[1]) * w1l;
                    part[mt][1] += (ch * E[2] + sh * O[2]) * w0h
                                 + (ch * E[3] + sh * O[3]) * w1h;
                }
            }
#pragma unroll
            for (int o = 1; o <= 2; o <<= 1)
#pragma unroll
                for (int mt = 0; mt < 4; ++mt) {
                    part[mt][0] += __shfl_xor_sync(0xffffffffu, part[mt][0], o);
                    part[mt][1] += __shfl_xor_sync(0xffffffffu, part[mt][1], o);
                }
            if (q4 == 0) {
#pragma unroll
                for (int mt = 0; mt < 4; ++mt) {
                    red[wd * 64 + mt * 16 + g4]     = part[mt][0];
                    red[wd * 64 + mt * 16 + g4 + 8] = part[mt][1];
                }
            }
            __syncthreads();
            if (tid < BM) {
                float tot = 0.f;
#pragma unroll
                for (int ww = 0; ww < 8; ++ww) tot += red[ww * 64 + tid];
#pragma unroll
                for (int o = 0; o < OUT_; ++o)
                    out[(size_t)(b0 + tid) * OUT_ + o] =
                        tot * __ldg(&w[o]) + __ldg(&bias[o]);
            }
        }
    }
#undef BODY
#undef SWEEP
#undef LOADB
}

// ============================================================================
// Launch: 3 kernels.
// ============================================================================
extern "C" void kernel_launch(void* const* d_in, const int* in_sizes, int n_in,
                              void* d_out, int out_size) {
    const float* x     = (const float*)d_in[0];  // [B, N]
    const float* first = (const float*)d_in[1];  // [1, 2, D]
    const float* mid   = (const float*)d_in[2];  // [N-2, D, 2, D]
    const float* last  = (const float*)d_in[3];  // [D, 2, 1]
    const float* w     = (const float*)d_in[4];  // [OUT, 1]
    const float* bias  = (const float*)d_in[5];  // [OUT]
    float* out = (float*)d_out;                  // [B, OUT]

    phi_kernel<<<B_ / 8, 256>>>(x);
    split_mid_kernel<<<(NSTEP * 32768 + 255) / 256, 256>>>(mid);
    mps_hmma_kernel<<<NCTA, THREADS>>>(first, last, w, bias, out);
}

// round 9
// speedup vs baseline: 9.0912x; 1.1381x over previous
#include <cuda_runtime.h>
#include <cuda_bf16.h>
#include <cstdint>

// Problem constants
#define B_     8192
#define NSITE  256
#define D_     128
#define OUT_   10
#define NSTEP  254
#define BM     64            // samples per CTA
#define NCTA   (B_ / BM)     // 128 CTAs
#define THREADS 256          // 8 warps, N-split only

// Dynamic smem layout (bytes): A double-buffer + staging
//   A buf b at b*32768 (AH +0, AL +16384)
#define SM_FL   65536        // float staging area begins here
#define SMEM_TOTAL (SM_FL + 1152 * 4)

// Scratch globals
__device__ float g_cos[NSITE * B_];                      // 8 MB
__device__ float g_sin[NSITE * B_];                      // 8 MB
// Fragment-major pre-split B: per step 8192 uint4 chunks laid out so that
// uint4 index = [step:*][c2:3][w:3][ldg:2][lane:5]  (ldg = mat*2 + parity)
__device__ __nv_bfloat16 g_B[(size_t)NSTEP * 65536];     // 33.3 MB

// ---------------------------------------------------------------------------
// Base-ISA asm helpers
// ---------------------------------------------------------------------------
__device__ __forceinline__ uint32_t smem_u32(const void* p) {
    uint32_t a;
    asm("{ .reg .u64 t; cvta.to.shared.u64 t, %1; cvt.u32.u64 %0, t; }"
        : "=r"(a) : "l"(p));
    return a;
}
__device__ __forceinline__ void ldsm4(uint32_t* r, uint32_t a) {
    asm volatile("ldmatrix.sync.aligned.m8n8.x4.shared.b16 {%0,%1,%2,%3}, [%4];"
                 : "=r"(r[0]), "=r"(r[1]), "=r"(r[2]), "=r"(r[3]) : "r"(a));
}
__device__ __forceinline__ void stsm4(uint32_t a, uint32_t r0, uint32_t r1,
                                      uint32_t r2, uint32_t r3) {
    asm volatile("stmatrix.sync.aligned.m8n8.x4.shared.b16 [%0], {%1,%2,%3,%4};"
                 :: "r"(a), "r"(r0), "r"(r1), "r"(r2), "r"(r3) : "memory");
}
__device__ __forceinline__ void mma16816(float* c, const uint32_t* a,
                                         const uint32_t* b) {
    asm volatile(
        "mma.sync.aligned.m16n8k16.row.col.f32.bf16.bf16.f32 "
        "{%0,%1,%2,%3}, {%4,%5,%6,%7}, {%8,%9}, {%0,%1,%2,%3};"
        : "+f"(c[0]), "+f"(c[1]), "+f"(c[2]), "+f"(c[3])
        : "r"(a[0]), "r"(a[1]), "r"(a[2]), "r"(a[3]), "r"(b[0]), "r"(b[1]));
}
// hi/lo bf16 split of (r0, r1) -> packed bf16x2 (low half = r0)
__device__ __forceinline__ void split2(float r0, float r1,
                                       uint32_t& h, uint32_t& l) {
    uint32_t hp;
    asm("cvt.rn.satfinite.bf16x2.f32 %0, %1, %2;" : "=r"(hp) : "f"(r1), "f"(r0));
    float f0 = __uint_as_float(hp << 16);
    float f1 = __uint_as_float(hp & 0xFFFF0000u);
    float l0 = r0 - f0, l1 = r1 - f1;
    uint32_t lp;
    asm("cvt.rn.satfinite.bf16x2.f32 %0, %1, %2;" : "=r"(lp) : "f"(l1), "f"(l0));
    h = hp; l = lp;
}

// ============================================================================
// Kernel 1: feature map. Smem-staged transposed writes: each output store
// instruction covers 4 sites x 8 consecutive samples (32B sectors) instead of
// 32 scattered sectors.
// ============================================================================
__global__ void phi_kernel(const float* __restrict__ x) {
    __shared__ float smc[NSITE * 8];
    __shared__ float sms[NSITE * 8];
    int wid  = threadIdx.x >> 5;         // 8 warps = 8 samples per block
    int lane = threadIdx.x & 31;
    int b0   = blockIdx.x * 8;
    const float* xr = x + (size_t)(b0 + wid) * NSITE;

    float v[8];
    float mn = 3.402823466e38f, mx = -3.402823466e38f;
#pragma unroll
    for (int i = 0; i < 8; i++) {
        v[i] = xr[lane + i * 32];
        mn = fminf(mn, v[i]);
        mx = fmaxf(mx, v[i]);
    }
#pragma unroll
    for (int o = 16; o; o >>= 1) {
        mn = fminf(mn, __shfl_xor_sync(0xffffffffu, mn, o));
        mx = fmaxf(mx, __shfl_xor_sync(0xffffffffu, mx, o));
    }
    float inv = 1.0f / (mx - mn + 1e-6f);
#pragma unroll
    for (int i = 0; i < 8; i++) {
        float ang = 1.57079632679f * ((v[i] - mn) * inv);
        float s, c;
        __sincosf(ang, &s, &c);
        int site = lane + i * 32;
        smc[site * 8 + wid] = c;
        sms[site * 8 + wid] = s;
    }
    __syncthreads();
#pragma unroll
    for (int i = threadIdx.x; i < NSITE * 8; i += THREADS) {
        int site = i >> 3, o = i & 7;
        g_cos[(size_t)site * B_ + b0 + o] = smc[i];
        g_sin[(size_t)site * B_ + b0 + o] = sms[i];
    }
}

// ============================================================================
// Kernel 2: split mid into bf16 hi/lo, fragment-major. Output-centric: one
// thread builds one 16B chunk; output uint4 index == global thread index.
// ============================================================================
__global__ void split_mid_kernel(const float* __restrict__ mid) {
    int idx = blockIdx.x * blockDim.x + threadIdx.x;
    if (idx >= NSTEP * 8192) return;
    int step = idx >> 13;
    int rem  = idx & 8191;
    int c2   = rem >> 10;          // k-chunk 0..7
    int w    = (rem >> 7) & 7;     // warp / n-strip
    int ldgi = (rem >> 5) & 3;     // mat*2 + parity
    int lane = rem & 31;
    int mat = ldgi >> 1, d = ldgi & 1;
    int nn = lane >> 2, kq = lane & 3;

    uint32_t outv[4];
#pragma unroll
    for (int n8 = 0; n8 < 2; ++n8)
#pragma unroll
        for (int rk = 0; rk < 2; ++rk) {
            uint32_t u = 0;
#pragma unroll
            for (int half = 0; half < 2; ++half) {
                int l = c2 * 16 + rk * 8 + kq * 2 + half;
                int n = w * 16 + n8 * 8 + nn;
                float v = mid[(((size_t)step * 128 + l) * 2 + d) * 128 + n];
                __nv_bfloat16 bh = __float2bfloat16(v);
                uint16_t bits;
                if (mat == 0) {
                    bits = *(uint16_t*)&bh;
                } else {
                    float fh = __bfloat162float(bh);
                    __nv_bfloat16 bl = __float2bfloat16(v - fh);
                    bits = *(uint16_t*)&bl;
                }
                u |= (uint32_t)bits << (half * 16);
            }
            outv[n8 * 2 + rk] = u;
        }
    ((uint4*)g_B)[idx] = make_uint4(outv[0], outv[1], outv[2], outv[3]);
}

// ============================================================================
// Kernel 3: HMMA MPS chain. One barrier per step, A double-buffered in smem.
// Chunk order per warp rotated so chunk 0 == the warp's OWN n-slice (= next
// A's k-slice): its A-fragments come straight from last epilogue's registers
// (D-frag layout == A-frag layout), so MMAs start immediately after the
// barrier with no ldsm dependency.
// ============================================================================
__global__ __launch_bounds__(THREADS, 1)
void mps_hmma_kernel(const float* __restrict__ first,
                     const float* __restrict__ last,
                     const float* __restrict__ w,
                     const float* __restrict__ bias,
                     float* __restrict__ out) {
    extern __shared__ __align__(1024) char smem[];
    const uint32_t sb = smem_u32(smem);
    float* fl    = (float*)(smem + SM_FL);
    float* cS    = fl;            // [2][64] (slot, staged one step ahead)
    float* sS    = fl + 128;      // [2][64]
    float* c2S   = fl + 256;      // [64] site 255
    float* s2S   = fl + 320;
    float* lastS = fl + 384;      // [256]
    float* red   = fl + 640;      // [512]

    const int tid  = threadIdx.x;
    const int lane = tid & 31;
    const int wd   = tid >> 5;     // warp = n-strip 0..7 (16 phys cols)
    const int gA   = lane >> 3;
    const int rowA = lane & 7;
    const int g4   = lane >> 2;
    const int q4   = lane & 3;
    const int b0   = blockIdx.x * BM;

    lastS[tid] = __ldg(&last[tid]);

    uint4 Bb0[4], Bb1[4];
#define LOADB(R, step_, c_) do {                                             \
    const uint4* _p = (const uint4*)(g_B + (size_t)(step_) * 65536)          \
                    + ((c_) * 8 + wd) * 128 + lane;                          \
    R[0] = __ldg(_p); R[1] = __ldg(_p + 32);                                 \
    R[2] = __ldg(_p + 64); R[3] = __ldg(_p + 96);                            \
} while (0)

    LOADB(Bb0, 0, wd);

    // ---- A0 full tile into buf 0 ----
    for (int i = tid; i < BM * D_; i += THREADS) {
        int r = i >> 7, k = i & 127;
        float c0 = __ldg(&g_cos[b0 + r]);
        float s0 = __ldg(&g_sin[b0 + r]);
        float v = __ldg(&first[k]) * c0 + __ldg(&first[D_ + k]) * s0;
        __nv_bfloat16 bh = __float2bfloat16(v);
        float fh = __bfloat162float(bh);
        __nv_bfloat16 bl = __float2bfloat16(v - fh);
        int el = ((r >> 3) * 16 + (k >> 3)) * 64 + (r & 7) * 8 + (k & 7);
        ((__nv_bfloat16*)smem)[el]        = bh;   // buf0 AH
        ((__nv_bfloat16*)smem)[8192 + el] = bl;   // buf0 AL (16384 B offset)
    }

    // ---- held local A-frags for step 0 (chunk wd), computed directly ----
    uint32_t aHloc[4][4], aLloc[4][4];
#pragma unroll
    for (int mt = 0; mt < 4; ++mt) {
        int r1 = mt * 16 + g4, r2 = r1 + 8;
        float c1 = __ldg(&g_cos[b0 + r1]), s1 = __ldg(&g_sin[b0 + r1]);
        float c2_ = __ldg(&g_cos[b0 + r2]), s2_ = __ldg(&g_sin[b0 + r2]);
#pragma unroll
        for (int n8 = 0; n8 < 2; ++n8) {
            int k0 = wd * 16 + n8 * 8 + 2 * q4;
            float f0 = __ldg(&first[k0]),     g0 = __ldg(&first[128 + k0]);
            float f1 = __ldg(&first[k0 + 1]), g1 = __ldg(&first[129 + k0]);
            split2(f0 * c1 + g0 * s1, f1 * c1 + g1 * s1,
                   aHloc[mt][n8 * 2], aLloc[mt][n8 * 2]);
            split2(f0 * c2_ + g0 * s2_, f1 * c2_ + g1 * s2_,
                   aHloc[mt][n8 * 2 + 1], aLloc[mt][n8 * 2 + 1]);
        }
    }

    // pre-stage phi site 1 into slot 1
    if (tid < BM) {
        cS[64 + tid] = __ldg(&g_cos[(size_t)B_ + b0 + tid]);
        sS[64 + tid] = __ldg(&g_sin[(size_t)B_ + b0 + tid]);
    }
    __syncthreads();

#define SWEEP(AF, MB, CUR)                                                   \
    _Pragma("unroll") for (int mt = 0; mt < 4; ++mt)                         \
    _Pragma("unroll") for (int d2 = 0; d2 < 2; ++d2)                         \
    _Pragma("unroll") for (int n8 = 0; n8 < 2; ++n8) {                       \
        const int f = (MB) + d2 * 2 + n8;                                    \
        mma16816(acc[mt][d2][n8], AF[mt],                                    \
                 (const uint32_t*)&CUR[f >> 1] + (f & 1) * 2);               \
    }

#define BODY(jv, CUR, NXT) {                                                 \
    const int c_ = (wd + (jv)) & 7;                                          \
    if ((jv) < 7)             LOADB(NXT, m, (wd + (jv) + 1) & 7);            \
    else if (m < NSTEP - 1)   LOADB(NXT, m + 1, wd);                         \
    uint32_t aH[4][4], aL[4][4];                                             \
    _Pragma("unroll") for (int mt = 0; mt < 4; ++mt) {                       \
        uint32_t off = (uint32_t)(((mt * 2 + (gA & 1)) * 16 +                \
                       (c_ * 2 + (gA >> 1))) * 128 + rowA * 16);             \
        ldsm4(aH[mt], sb + acur + off);                                      \
        ldsm4(aL[mt], sb + acur + 16384 + off);                              \
    }                                                                        \
    SWEEP(aH, 0, CUR)                                                        \
    SWEEP(aL, 0, CUR)                                                        \
    SWEEP(aH, 4, CUR)                                                        \
}

    // ---- site loop: ONE barrier per step ----
#pragma unroll 1
    for (int m = 0; m < NSTEP; ++m) {
        const uint32_t acur = (uint32_t)((m & 1) * 32768);
        const uint32_t anxt = acur ^ 32768u;

        float acc[4][2][2][4];
#pragma unroll
        for (int mt = 0; mt < 4; ++mt)
#pragma unroll
            for (int d2 = 0; d2 < 2; ++d2)
#pragma unroll
                for (int n8 = 0; n8 < 2; ++n8)
#pragma unroll
                    for (int q = 0; q < 4; ++q) acc[mt][d2][n8][q] = 0.0f;

        // j = 0: local chunk from held registers (no ldsm, no wait)
        {
            LOADB(Bb1, m, (wd + 1) & 7);
            if (tid < BM) {   // stage phi site m+2 into slot m&1
                cS[(m & 1) * 64 + tid] =
                    __ldg(&g_cos[(size_t)(m + 2) * B_ + b0 + tid]);
                sS[(m & 1) * 64 + tid] =
                    __ldg(&g_sin[(size_t)(m + 2) * B_ + b0 + tid]);
            }
            if (m == NSTEP - 2 && tid >= 64 && tid < 128) {
                int t = tid - 64;
                c2S[t] = __ldg(&g_cos[(size_t)(NSITE - 1) * B_ + b0 + t]);
                s2S[t] = __ldg(&g_sin[(size_t)(NSITE - 1) * B_ + b0 + t]);
            }
            SWEEP(aHloc, 0, Bb0)
            SWEEP(aLloc, 0, Bb0)
            SWEEP(aHloc, 4, Bb0)
        }
        BODY(1, Bb1, Bb0)
        BODY(2, Bb0, Bb1)
        BODY(3, Bb1, Bb0)
        BODY(4, Bb0, Bb1)
        BODY(5, Bb1, Bb0)
        BODY(6, Bb0, Bb1)
        BODY(7, Bb1, Bb0)

        const int slot = ((m + 1) & 1) * 64;
        if (m < NSTEP - 1) {
            // ---- epilogue: combine parity, split hi/lo; keep local frags,
            //      stsm full slice into the NEXT A buffer ----
#pragma unroll
            for (int mt = 0; mt < 4; ++mt) {
                float cl = cS[slot + mt * 16 + g4];
                float ch = cS[slot + mt * 16 + g4 + 8];
                float sl = sS[slot + mt * 16 + g4];
                float sh = sS[slot + mt * 16 + g4 + 8];
#pragma unroll
                for (int n8 = 0; n8 < 2; ++n8) {
                    float* E = acc[mt][0][n8];
                    float* O = acc[mt][1][n8];
                    split2(cl * E[0] + sl * O[0], cl * E[1] + sl * O[1],
                           aHloc[mt][n8 * 2], aLloc[mt][n8 * 2]);
                    split2(ch * E[2] + sh * O[2], ch * E[3] + sh * O[3],
                           aHloc[mt][n8 * 2 + 1], aLloc[mt][n8 * 2 + 1]);
                }
                uint32_t off = (uint32_t)(((mt * 2 + (gA & 1)) * 16 +
                               (wd * 2 + (gA >> 1))) * 128 + rowA * 16);
                stsm4(sb + anxt + off, aHloc[mt][0], aHloc[mt][1],
                      aHloc[mt][2], aHloc[mt][3]);
                stsm4(sb + anxt + 16384 + off, aLloc[mt][0], aLloc[mt][1],
                      aLloc[mt][2], aLloc[mt][3]);
            }
        } else {
            // ---- final: contract with last site + linear head ----
            float part[4][2];
#pragma unroll
            for (int mt = 0; mt < 4; ++mt) { part[mt][0] = 0.f; part[mt][1] = 0.f; }
#pragma unroll
            for (int mt = 0; mt < 4; ++mt) {
                float cl = cS[slot + mt * 16 + g4];
                float ch = cS[slot + mt * 16 + g4 + 8];
                float sl = sS[slot + mt * 16 + g4];
                float sh = sS[slot + mt * 16 + g4 + 8];
                float c2l = c2S[mt * 16 + g4], c2h = c2S[mt * 16 + g4 + 8];
                float s2l = s2S[mt * 16 + g4], s2h = s2S[mt * 16 + g4 + 8];
#pragma unroll
                for (int n8 = 0; n8 < 2; ++n8) {
                    float* E = acc[mt][0][n8];
                    float* O = acc[mt][1][n8];
                    int n0 = wd * 16 + n8 * 8 + 2 * q4;
                    float w0l = lastS[2 * n0] * c2l + lastS[2 * n0 + 1] * s2l;
                    float w1l = lastS[2 * n0 + 2] * c2l + lastS[2 * n0 + 3] * s2l;
                    float w0h = lastS[2 * n0] * c2h + lastS[2 * n0 + 1] * s2h;
                    float w1h = lastS[2 * n0 + 2] * c2h + lastS[2 * n0 + 3] * s2h;
                    part[mt][0] += (cl * E[0] + sl * O[0]) * w0l
                                 + (cl * E[1] + sl * O[1]) * w1l;
                    part[mt][1] += (ch * E[2] + sh * O[2]) * w0h
                                 + (ch * E[3] + sh * O[3]) * w1h;
                }
            }
#pragma unroll
            for (int o = 1; o <= 2; o <<= 1)
#pragma unroll
                for (int mt = 0; mt < 4; ++mt) {
                    part[mt][0] += __shfl_xor_sync(0xffffffffu, part[mt][0], o);
                    part[mt][1] += __shfl_xor_sync(0xffffffffu, part[mt][1], o);
                }
            if (q4 == 0) {
#pragma unroll
                for (int mt = 0; mt < 4; ++mt) {
                    red[wd * 64 + mt * 16 + g4]     = part[mt][0];
                    red[wd * 64 + mt * 16 + g4 + 8] = part[mt][1];
                }
            }
            __syncthreads();
            if (tid < BM) {
                float tot = 0.f;
#pragma unroll
                for (int ww = 0; ww < 8; ++ww) tot += red[ww * 64 + tid];
#pragma unroll
                for (int o = 0; o < OUT_; ++o)
                    out[(size_t)(b0 + tid) * OUT_ + o] =
                        tot * __ldg(&w[o]) + __ldg(&bias[o]);
            }
        }
        __syncthreads();   // new A visible; old A reads all complete
    }
#undef BODY
#undef SWEEP
#undef LOADB
}

// ============================================================================
// Launch: 3 kernels.
// ============================================================================
extern "C" void kernel_launch(void* const* d_in, const int* in_sizes, int n_in,
                              void* d_out, int out_size) {
    const float* x     = (const float*)d_in[0];  // [B, N]
    const float* first = (const float*)d_in[1];  // [1, 2, D]
    const float* mid   = (const float*)d_in[2];  // [N-2, D, 2, D]
    const float* last  = (const float*)d_in[3];  // [D, 2, 1]
    const float* w     = (const float*)d_in[4];  // [OUT, 1]
    const float* bias  = (const float*)d_in[5];  // [OUT]
    float* out = (float*)d_out;                  // [B, OUT]

    cudaFuncSetAttribute(mps_hmma_kernel,
                         cudaFuncAttributeMaxDynamicSharedMemorySize,
                         SMEM_TOTAL);

    phi_kernel<<<B_ / 8, THREADS>>>(x);
    split_mid_kernel<<<(NSTEP * 8192 + 255) / 256, 256>>>(mid);
    mps_hmma_kernel<<<NCTA, THREADS, SMEM_TOTAL>>>(first, last, w, bias, out);
}

// round 10
// speedup vs baseline: 9.7148x; 1.0686x over previous
#include <cuda_runtime.h>
#include <cuda_bf16.h>
#include <cstdint>

// Problem constants
#define B_     8192
#define NSITE  256
#define D_     128
#define OUT_   10
#define NSTEP  254
#define BM     64            // samples per CTA
#define NCTA   (B_ / BM)     // 128 CTAs
#define THREADS 256          // 8 warps, N-split only

// Dynamic smem layout (bytes): A double-buffer + staging + mbarrier
#define SM_FL   65536        // float staging area begins here
#define SM_MB   (SM_FL + 4608)
#define SMEM_TOTAL (SM_MB + 16)

// Scratch globals
__device__ float g_cos[NSITE * B_];                      // 8 MB
__device__ float g_sin[NSITE * B_];                      // 8 MB
// Fragment-major pre-split B: per step 8192 uint4 chunks laid out so that
// uint4 index = [step:*][c2:3][w:3][ldg:2][lane:5]  (ldg = mat*2 + parity)
__device__ __nv_bfloat16 g_B[(size_t)NSTEP * 65536];     // 33.3 MB

// ---------------------------------------------------------------------------
// Base-ISA asm helpers
// ---------------------------------------------------------------------------
__device__ __forceinline__ uint32_t smem_u32(const void* p) {
    uint32_t a;
    asm("{ .reg .u64 t; cvta.to.shared.u64 t, %1; cvt.u32.u64 %0, t; }"
        : "=r"(a) : "l"(p));
    return a;
}
__device__ __forceinline__ void ldsm4(uint32_t* r, uint32_t a) {
    asm volatile("ldmatrix.sync.aligned.m8n8.x4.shared.b16 {%0,%1,%2,%3}, [%4];"
                 : "=r"(r[0]), "=r"(r[1]), "=r"(r[2]), "=r"(r[3]) : "r"(a));
}
__device__ __forceinline__ void stsm4(uint32_t a, uint32_t r0, uint32_t r1,
                                      uint32_t r2, uint32_t r3) {
    asm volatile("stmatrix.sync.aligned.m8n8.x4.shared.b16 [%0], {%1,%2,%3,%4};"
                 :: "r"(a), "r"(r0), "r"(r1), "r"(r2), "r"(r3) : "memory");
}
__device__ __forceinline__ void mma16816(float* c, const uint32_t* a,
                                         const uint32_t* b) {
    asm volatile(
        "mma.sync.aligned.m16n8k16.row.col.f32.bf16.bf16.f32 "
        "{%0,%1,%2,%3}, {%4,%5,%6,%7}, {%8,%9}, {%0,%1,%2,%3};"
        : "+f"(c[0]), "+f"(c[1]), "+f"(c[2]), "+f"(c[3])
        : "r"(a[0]), "r"(a[1]), "r"(a[2]), "r"(a[3]), "r"(b[0]), "r"(b[1]));
}
__device__ __forceinline__ void split2(float r0, float r1,
                                       uint32_t& h, uint32_t& l) {
    uint32_t hp;
    asm("cvt.rn.satfinite.bf16x2.f32 %0, %1, %2;" : "=r"(hp) : "f"(r1), "f"(r0));
    float f0 = __uint_as_float(hp << 16);
    float f1 = __uint_as_float(hp & 0xFFFF0000u);
    float l0 = r0 - f0, l1 = r1 - f1;
    uint32_t lp;
    asm("cvt.rn.satfinite.bf16x2.f32 %0, %1, %2;" : "=r"(lp) : "f"(l1), "f"(l0));
    h = hp; l = lp;
}
__device__ __forceinline__ void mbar_init(uint32_t mb, uint32_t cnt) {
    asm volatile("mbarrier.init.shared.b64 [%0], %1;" :: "r"(mb), "r"(cnt)
                 : "memory");
}
__device__ __forceinline__ void mbar_arrive(uint32_t mb) {
    asm volatile("mbarrier.arrive.shared.b64 _, [%0];" :: "r"(mb) : "memory");
}
__device__ __forceinline__ void mbar_wait(uint32_t mb, uint32_t parity) {
    asm volatile(
        "{\n\t.reg .pred P1;\n\t"
        "WAIT_LOOP_%=:\n\t"
        "mbarrier.try_wait.parity.acquire.cta.shared::cta.b64 P1, [%0], %1, 0x989680;\n\t"
        "@P1 bra.uni WAIT_DONE_%=;\n\t"
        "bra.uni WAIT_LOOP_%=;\n\t"
        "WAIT_DONE_%=:\n\t}"
        :: "r"(mb), "r"(parity) : "memory");
}

// ============================================================================
// Kernel 1 (fused prep): blocks [0,1024) = feature map; blocks [1024, 9152)
// = mid split into bf16 hi/lo fragment-major chunks. Both 256 threads.
// ============================================================================
__global__ void prep_kernel(const float* __restrict__ x,
                            const float* __restrict__ mid) {
    __shared__ float smc[NSITE * 8];
    __shared__ float sms[NSITE * 8];
    if (blockIdx.x < 1024) {
        // ---- feature map, smem-staged transposed writes ----
        int wid  = threadIdx.x >> 5;
        int lane = threadIdx.x & 31;
        int b0   = blockIdx.x * 8;
        const float* xr = x + (size_t)(b0 + wid) * NSITE;

        float v[8];
        float mn = 3.402823466e38f, mx = -3.402823466e38f;
#pragma unroll
        for (int i = 0; i < 8; i++) {
            v[i] = xr[lane + i * 32];
            mn = fminf(mn, v[i]);
            mx = fmaxf(mx, v[i]);
        }
#pragma unroll
        for (int o = 16; o; o >>= 1) {
            mn = fminf(mn, __shfl_xor_sync(0xffffffffu, mn, o));
            mx = fmaxf(mx, __shfl_xor_sync(0xffffffffu, mx, o));
        }
        float inv = 1.0f / (mx - mn + 1e-6f);
#pragma unroll
        for (int i = 0; i < 8; i++) {
            float ang = 1.57079632679f * ((v[i] - mn) * inv);
            float s, c;
            __sincosf(ang, &s, &c);
            int site = lane + i * 32;
            smc[site * 8 + wid] = c;
            sms[site * 8 + wid] = s;
        }
        __syncthreads();
#pragma unroll
        for (int i = threadIdx.x; i < NSITE * 8; i += THREADS) {
            int site = i >> 3, o = i & 7;
            g_cos[(size_t)site * B_ + b0 + o] = smc[i];
            g_sin[(size_t)site * B_ + b0 + o] = sms[i];
        }
    } else {
        // ---- mid split, output-centric (uint4 index == thread index) ----
        int idx = (blockIdx.x - 1024) * blockDim.x + threadIdx.x;
        if (idx >= NSTEP * 8192) return;
        int step = idx >> 13;
        int rem  = idx & 8191;
        int c2   = rem >> 10;
        int w    = (rem >> 7) & 7;
        int ldgi = (rem >> 5) & 3;
        int lane = rem & 31;
        int mat = ldgi >> 1, d = ldgi & 1;
        int nn = lane >> 2, kq = lane & 3;

        uint32_t outv[4];
#pragma unroll
        for (int n8 = 0; n8 < 2; ++n8)
#pragma unroll
            for (int rk = 0; rk < 2; ++rk) {
                uint32_t u = 0;
#pragma unroll
                for (int half = 0; half < 2; ++half) {
                    int l = c2 * 16 + rk * 8 + kq * 2 + half;
                    int n = w * 16 + n8 * 8 + nn;
                    float v = mid[(((size_t)step * 128 + l) * 2 + d) * 128 + n];
                    __nv_bfloat16 bh = __float2bfloat16(v);
                    uint16_t bits;
                    if (mat == 0) {
                        bits = *(uint16_t*)&bh;
                    } else {
                        float fh = __bfloat162float(bh);
                        __nv_bfloat16 bl = __float2bfloat16(v - fh);
                        bits = *(uint16_t*)&bl;
                    }
                    u |= (uint32_t)bits << (half * 16);
                }
                outv[n8 * 2 + rk] = u;
            }
        ((uint4*)g_B)[idx] = make_uint4(outv[0], outv[1], outv[2], outv[3]);
    }
}

// ============================================================================
// Kernel 2: HMMA MPS chain with SPLIT-PHASE step barrier (mbarrier):
// arrive posted right after each warp's epilogue stsm; acquire-wait sits
// AFTER next step's j=0 MMAs (which use held registers only). The j=0
// tensor work absorbs epilogue skew + barrier latency.
// ============================================================================
__global__ __launch_bounds__(THREADS, 1)
void mps_hmma_kernel(const float* __restrict__ first,
                     const float* __restrict__ last,
                     const float* __restrict__ w,
                     const float* __restrict__ bias,
                     float* __restrict__ out) {
    extern __shared__ __align__(1024) char smem[];
    const uint32_t sb = smem_u32(smem);
    const uint32_t mb = sb + SM_MB;
    float* fl    = (float*)(smem + SM_FL);
    float* cS    = fl;            // [2][64]
    float* sS    = fl + 128;      // [2][64]
    float* c2S   = fl + 256;      // [64] site 255
    float* s2S   = fl + 320;
    float* lastS = fl + 384;      // [256]
    float* red   = fl + 640;      // [512]

    const int tid  = threadIdx.x;
    const int lane = tid & 31;
    const int wd   = tid >> 5;
    const int gA   = lane >> 3;
    const int rowA = lane & 7;
    const int g4   = lane >> 2;
    const int q4   = lane & 3;
    const int b0   = blockIdx.x * BM;

    lastS[tid] = __ldg(&last[tid]);

    uint4 Bb0[4], Bb1[4];
#define LOADB(R, step_, c_) do {                                             \
    const uint4* _p = (const uint4*)(g_B + (size_t)(step_) * 65536)          \
                    + ((c_) * 8 + wd) * 128 + lane;                          \
    R[0] = __ldg(_p); R[1] = __ldg(_p + 32);                                 \
    R[2] = __ldg(_p + 64); R[3] = __ldg(_p + 96);                            \
} while (0)

    LOADB(Bb0, 0, wd);

    // ---- A0 full tile into buf 0 ----
    for (int i = tid; i < BM * D_; i += THREADS) {
        int r = i >> 7, k = i & 127;
        float c0 = __ldg(&g_cos[b0 + r]);
        float s0 = __ldg(&g_sin[b0 + r]);
        float v = __ldg(&first[k]) * c0 + __ldg(&first[D_ + k]) * s0;
        __nv_bfloat16 bh = __float2bfloat16(v);
        float fh = __bfloat162float(bh);
        __nv_bfloat16 bl = __float2bfloat16(v - fh);
        int el = ((r >> 3) * 16 + (k >> 3)) * 64 + (r & 7) * 8 + (k & 7);
        ((__nv_bfloat16*)smem)[el]        = bh;
        ((__nv_bfloat16*)smem)[8192 + el] = bl;
    }

    // ---- held local A-frags for step 0 (chunk wd) ----
    uint32_t aHloc[4][4], aLloc[4][4];
#pragma unroll
    for (int mt = 0; mt < 4; ++mt) {
        int r1 = mt * 16 + g4, r2 = r1 + 8;
        float c1 = __ldg(&g_cos[b0 + r1]), s1 = __ldg(&g_sin[b0 + r1]);
        float c2_ = __ldg(&g_cos[b0 + r2]), s2_ = __ldg(&g_sin[b0 + r2]);
#pragma unroll
        for (int n8 = 0; n8 < 2; ++n8) {
            int k0 = wd * 16 + n8 * 8 + 2 * q4;
            float f0 = __ldg(&first[k0]),     g0 = __ldg(&first[128 + k0]);
            float f1 = __ldg(&first[k0 + 1]), g1 = __ldg(&first[129 + k0]);
            split2(f0 * c1 + g0 * s1, f1 * c1 + g1 * s1,
                   aHloc[mt][n8 * 2], aLloc[mt][n8 * 2]);
            split2(f0 * c2_ + g0 * s2_, f1 * c2_ + g1 * s2_,
                   aHloc[mt][n8 * 2 + 1], aLloc[mt][n8 * 2 + 1]);
        }
    }

    // pre-stage phi site 1 into slot 1
    if (tid < BM) {
        cS[64 + tid] = __ldg(&g_cos[(size_t)B_ + b0 + tid]);
        sS[64 + tid] = __ldg(&g_sin[(size_t)B_ + b0 + tid]);
    }
    if (tid == 0) mbar_init(mb, THREADS);
    __syncthreads();
    mbar_arrive(mb);           // completes phase 0 (prologue published)

#define SWEEP(AF, MB_, CUR)                                                  \
    _Pragma("unroll") for (int mt = 0; mt < 4; ++mt)                         \
    _Pragma("unroll") for (int d2 = 0; d2 < 2; ++d2)                         \
    _Pragma("unroll") for (int n8 = 0; n8 < 2; ++n8) {                       \
        const int f = (MB_) + d2 * 2 + n8;                                   \
        mma16816(acc[mt][d2][n8], AF[mt],                                    \
                 (const uint32_t*)&CUR[f >> 1] + (f & 1) * 2);               \
    }

#define BODY(jv, CUR, NXT) {                                                 \
    const int c_ = (wd + (jv)) & 7;                                          \
    if ((jv) < 7)             LOADB(NXT, m, (wd + (jv) + 1) & 7);            \
    else if (m < NSTEP - 1)   LOADB(NXT, m + 1, wd);                         \
    uint32_t aH[4][4], aL[4][4];                                             \
    _Pragma("unroll") for (int mt = 0; mt < 4; ++mt) {                       \
        uint32_t off = (uint32_t)(((mt * 2 + (gA & 1)) * 16 +                \
                       (c_ * 2 + (gA >> 1))) * 128 + rowA * 16);             \
        ldsm4(aH[mt], sb + acur + off);                                      \
        ldsm4(aL[mt], sb + acur + 16384 + off);                              \
    }                                                                        \
    SWEEP(aH, 0, CUR)                                                        \
    SWEEP(aL, 0, CUR)                                                        \
    SWEEP(aH, 4, CUR)                                                        \
}

    // ---- site loop: split-phase barrier per step ----
#pragma unroll 1
    for (int m = 0; m < NSTEP; ++m) {
        const uint32_t acur = (uint32_t)((m & 1) * 32768);
        const uint32_t anxt = acur ^ 32768u;

        float acc[4][2][2][4];
#pragma unroll
        for (int mt = 0; mt < 4; ++mt)
#pragma unroll
            for (int d2 = 0; d2 < 2; ++d2)
#pragma unroll
                for (int n8 = 0; n8 < 2; ++n8)
#pragma unroll
                    for (int q = 0; q < 4; ++q) acc[mt][d2][n8][q] = 0.0f;

        // j = 0: local chunk from held registers (no barrier needed)
        LOADB(Bb1, m, (wd + 1) & 7);
        SWEEP(aHloc, 0, Bb0)
        SWEEP(aLloc, 0, Bb0)
        SWEEP(aHloc, 4, Bb0)

        // wait: all warps' previous-step epilogues published
        mbar_wait(mb, (uint32_t)(m & 1));

        // stage phi site m+2 into slot m&1 (safe: post-wait)
        if (tid < BM) {
            cS[(m & 1) * 64 + tid] =
                __ldg(&g_cos[(size_t)(m + 2) * B_ + b0 + tid]);
            sS[(m & 1) * 64 + tid] =
                __ldg(&g_sin[(size_t)(m + 2) * B_ + b0 + tid]);
        }
        if (m == NSTEP - 2 && tid >= 64 && tid < 128) {
            int t = tid - 64;
            c2S[t] = __ldg(&g_cos[(size_t)(NSITE - 1) * B_ + b0 + t]);
            s2S[t] = __ldg(&g_sin[(size_t)(NSITE - 1) * B_ + b0 + t]);
        }

        BODY(1, Bb1, Bb0)
        BODY(2, Bb0, Bb1)
        BODY(3, Bb1, Bb0)
        BODY(4, Bb0, Bb1)
        BODY(5, Bb1, Bb0)
        BODY(6, Bb0, Bb1)
        BODY(7, Bb1, Bb0)

        const int slot = ((m + 1) & 1) * 64;
        if (m < NSTEP - 1) {
            // ---- epilogue: combine parity, split hi/lo, stsm; then arrive
#pragma unroll
            for (int mt = 0; mt < 4; ++mt) {
                float cl = cS[slot + mt * 16 + g4];
                float ch = cS[slot + mt * 16 + g4 + 8];
                float sl = sS[slot + mt * 16 + g4];
                float sh = sS[slot + mt * 16 + g4 + 8];
#pragma unroll
                for (int n8 = 0; n8 < 2; ++n8) {
                    float* E = acc[mt][0][n8];
                    float* O = acc[mt][1][n8];
                    split2(cl * E[0] + sl * O[0], cl * E[1] + sl * O[1],
                           aHloc[mt][n8 * 2], aLloc[mt][n8 * 2]);
                    split2(ch * E[2] + sh * O[2], ch * E[3] + sh * O[3],
                           aHloc[mt][n8 * 2 + 1], aLloc[mt][n8 * 2 + 1]);
                }
                uint32_t off = (uint32_t)(((mt * 2 + (gA & 1)) * 16 +
                               (wd * 2 + (gA >> 1))) * 128 + rowA * 16);
                stsm4(sb + anxt + off, aHloc[mt][0], aHloc[mt][1],
                      aHloc[mt][2], aHloc[mt][3]);
                stsm4(sb + anxt + 16384 + off, aLloc[mt][0], aLloc[mt][1],
                      aLloc[mt][2], aLloc[mt][3]);
            }
            mbar_arrive(mb);
        } else {
            // ---- final: contract with last site + linear head ----
            float part[4][2];
#pragma unroll
            for (int mt = 0; mt < 4; ++mt) { part[mt][0] = 0.f; part[mt][1] = 0.f; }
#pragma unroll
            for (int mt = 0; mt < 4; ++mt) {
                float cl = cS[slot + mt * 16 + g4];
                float ch = cS[slot + mt * 16 + g4 + 8];
                float sl = sS[slot + mt * 16 + g4];
                float sh = sS[slot + mt * 16 + g4 + 8];
                float c2l = c2S[mt * 16 + g4], c2h = c2S[mt * 16 + g4 + 8];
                float s2l = s2S[mt * 16 + g4], s2h = s2S[mt * 16 + g4 + 8];
#pragma unroll
                for (int n8 = 0; n8 < 2; ++n8) {
                    float* E = acc[mt][0][n8];
                    float* O = acc[mt][1][n8];
                    int n0 = wd * 16 + n8 * 8 + 2 * q4;
                    float w0l = lastS[2 * n0] * c2l + lastS[2 * n0 + 1] * s2l;
                    float w1l = lastS[2 * n0 + 2] * c2l + lastS[2 * n0 + 3] * s2l;
                    float w0h = lastS[2 * n0] * c2h + lastS[2 * n0 + 1] * s2h;
                    float w1h = lastS[2 * n0 + 2] * c2h + lastS[2 * n0 + 3] * s2h;
                    part[mt][0] += (cl * E[0] + sl * O[0]) * w0l
                                 + (cl * E[1] + sl * O[1]) * w1l;
                    part[mt][1] += (ch * E[2] + sh * O[2]) * w0h
                                 + (ch * E[3] + sh * O[3]) * w1h;
                }
            }
#pragma unroll
            for (int o = 1; o <= 2; o <<= 1)
#pragma unroll
                for (int mt = 0; mt < 4; ++mt) {
                    part[mt][0] += __shfl_xor_sync(0xffffffffu, part[mt][0], o);
                    part[mt][1] += __shfl_xor_sync(0xffffffffu, part[mt][1], o);
                }
            if (q4 == 0) {
#pragma unroll
                for (int mt = 0; mt < 4; ++mt) {
                    red[wd * 64 + mt * 16 + g4]     = part[mt][0];
                    red[wd * 64 + mt * 16 + g4 + 8] = part[mt][1];
                }
            }
            __syncthreads();
            if (tid < BM) {
                float tot = 0.f;
#pragma unroll
                for (int ww = 0; ww < 8; ++ww) tot += red[ww * 64 + tid];
#pragma unroll
                for (int o = 0; o < OUT_; ++o)
                    out[(size_t)(b0 + tid) * OUT_ + o] =
                        tot * __ldg(&w[o]) + __ldg(&bias[o]);
            }
        }
    }
#undef BODY
#undef SWEEP
#undef LOADB
}

// ============================================================================
// Launch: 2 kernels.
// ============================================================================
extern "C" void kernel_launch(void* const* d_in, const int* in_sizes, int n_in,
                              void* d_out, int out_size) {
    const float* x     = (const float*)d_in[0];  // [B, N]
    const float* first = (const float*)d_in[1];  // [1, 2, D]
    const float* mid   = (const float*)d_in[2];  // [N-2, D, 2, D]
    const float* last  = (const float*)d_in[3];  // [D, 2, 1]
    const float* w     = (const float*)d_in[4];  // [OUT, 1]
    const float* bias  = (const float*)d_in[5];  // [OUT]
    float* out = (float*)d_out;                  // [B, OUT]

    cudaFuncSetAttribute(mps_hmma_kernel,
                         cudaFuncAttributeMaxDynamicSharedMemorySize,
                         SMEM_TOTAL);

    prep_kernel<<<1024 + (NSTEP * 8192 + 255) / 256, THREADS>>>(x, mid);
    mps_hmma_kernel<<<NCTA, THREADS, SMEM_TOTAL>>>(first, last, w, bias, out);
}